// round 1
// baseline (speedup 1.0000x reference)
#include <cuda_runtime.h>
#include <math.h>

// Problem constants
#define BB 4
#define NN 2048
#define CC 1024
#define HH 16
#define DD 64
#define MM (BB * NN)          // 8192 rows
#define C3 (3 * CC)           // 3072
#define EPSV 1e-6f

// Scratch (static device allocations are the sanctioned way to get scratch)
__device__ float g_qkv[(size_t)MM * C3];   // [B,N,3,H,D] = [8192,3072]  (96 MB)
__device__ float g_o[(size_t)MM * CC];     // attention output in [B,N,C] (32 MB)

// ----------------------------------------------------------------------------
// Generic tiled fp32 GEMM:  C[M,N] = A[M,K] @ B[K,N] + bias[N]
// 64x64 tile, BK=16, 256 threads, 4x4 micro-tile per thread.
// ----------------------------------------------------------------------------
__global__ void gemm_bias_kernel(const float* __restrict__ A,
                                 const float* __restrict__ B,
                                 const float* __restrict__ bias,
                                 float* __restrict__ C,
                                 int M, int N, int K) {
    __shared__ float As[16][64];   // [k][m]
    __shared__ float Bs[16][64];   // [k][n]
    const int tid = threadIdx.x;
    const int tx = tid & 15;       // 0..15 -> n micro
    const int ty = tid >> 4;       // 0..15 -> m micro
    const int bm = blockIdx.y * 64;
    const int bn = blockIdx.x * 64;

    float acc[4][4];
#pragma unroll
    for (int i = 0; i < 4; i++)
#pragma unroll
        for (int j = 0; j < 4; j++) acc[i][j] = 0.f;

    for (int k0 = 0; k0 < K; k0 += 16) {
        // load A tile 64x16 (store transposed [k][m])
#pragma unroll
        for (int i = 0; i < 4; i++) {
            int e = tid + i * 256;
            int m = e >> 4, k = e & 15;
            As[k][m] = A[(size_t)(bm + m) * K + (k0 + k)];
        }
        // load B tile 16x64 (coalesced)
#pragma unroll
        for (int i = 0; i < 4; i++) {
            int e = tid + i * 256;
            int k = e >> 6, n = e & 63;
            Bs[k][n] = B[(size_t)(k0 + k) * N + (bn + n)];
        }
        __syncthreads();

#pragma unroll
        for (int k = 0; k < 16; k++) {
            float4 a4 = *reinterpret_cast<const float4*>(&As[k][ty * 4]);
            float4 b4 = *reinterpret_cast<const float4*>(&Bs[k][tx * 4]);
            float a[4] = {a4.x, a4.y, a4.z, a4.w};
            float b[4] = {b4.x, b4.y, b4.z, b4.w};
#pragma unroll
            for (int i = 0; i < 4; i++)
#pragma unroll
                for (int j = 0; j < 4; j++) acc[i][j] += a[i] * b[j];
        }
        __syncthreads();
    }

#pragma unroll
    for (int i = 0; i < 4; i++) {
        int m = bm + ty * 4 + i;
#pragma unroll
        for (int j = 0; j < 4; j++) {
            int n = bn + tx * 4 + j;
            C[(size_t)m * N + n] = acc[i][j] + bias[n];
        }
    }
}

// ----------------------------------------------------------------------------
// Head LayerNorm on q and k, in place inside g_qkv.
// One warp per (row, component). row in [0, B*N*H), component 0=q, 1=k.
// Each lane owns 2 of the 64 head-dim elements.
// ----------------------------------------------------------------------------
__global__ void qk_norm_kernel(const float* __restrict__ gamma_q,
                               const float* __restrict__ gamma_k) {
    int gwarp = (blockIdx.x * blockDim.x + threadIdx.x) >> 5;
    int lane = threadIdx.x & 31;
    // total warps = 2 * B*N*H = 262144
    int comp = gwarp & 1;
    int r = gwarp >> 1;            // [0, B*N*H)
    int h = r & (HH - 1);
    int bn = r >> 4;               // B*N index

    float* ptr = g_qkv + (size_t)bn * C3 + comp * CC + h * DD;
    float2 v = *reinterpret_cast<float2*>(ptr + lane * 2);

    float s = v.x + v.y;
#pragma unroll
    for (int off = 16; off >= 1; off >>= 1)
        s += __shfl_xor_sync(0xffffffffu, s, off);
    float mu = s * (1.0f / 64.0f);

    float dx = v.x - mu, dy = v.y - mu;
    float e = dx * dx + dy * dy;
#pragma unroll
    for (int off = 16; off >= 1; off >>= 1)
        e += __shfl_xor_sync(0xffffffffu, e, off);
    float rs = rsqrtf(e * (1.0f / 64.0f) + EPSV);

    const float* gamma = comp ? gamma_k : gamma_q;
    float2 o;
    o.x = dx * rs * gamma[lane * 2 + 0];
    o.y = dy * rs * gamma[lane * 2 + 1];
    *reinterpret_cast<float2*>(ptr + lane * 2) = o;
}

// ----------------------------------------------------------------------------
// Flash attention, fp32, D=64. One CTA = 64 q rows of one (b,h).
// Loops over 32 k-tiles of 64 rows with online softmax.
// smem: Qs[64][64], Kt[64][68] (transposed: [d][kv]), Vs[64][64], Ps[64][68].
// 256 threads; thread (ty,tx) owns 4x4 micro-tiles of S and O.
// Writes output directly in [B,N,H*D] layout into g_o.
// ----------------------------------------------------------------------------
#define SP 68
__global__ void flash_kernel() {
    extern __shared__ float sm[];
    float* Qs = sm;                    // 64*64
    float* Kt = Qs + 64 * 64;          // 64*SP   ([d][kv_row])
    float* Vs = Kt + 64 * SP;          // 64*64   ([kv_row][d])
    float* Ps = Vs + 64 * 64;          // 64*SP   ([q_row][kv_row])

    const int tid = threadIdx.x;
    const int tx = tid & 15;
    const int ty = tid >> 4;
    const int qt = blockIdx.x;         // q tile 0..31
    const int bh = blockIdx.y;         // 0..63
    const int b = bh >> 4;
    const int h = bh & 15;
    const float scale = 0.125f;        // D^-0.5

    // load Q tile (already layernormed): row n = qt*64 + r
    const size_t base_q = (size_t)(b * NN + qt * 64) * C3 + (size_t)h * DD;
#pragma unroll
    for (int i = 0; i < 16; i++) {
        int e = tid + i * 256;
        int r = e >> 6, d = e & 63;
        Qs[r * 64 + d] = g_qkv[base_q + (size_t)r * C3 + d];
    }

    float m_i[4], l_i[4], o_acc[4][4];
#pragma unroll
    for (int i = 0; i < 4; i++) {
        m_i[i] = -1e30f;
        l_i[i] = 0.f;
#pragma unroll
        for (int j = 0; j < 4; j++) o_acc[i][j] = 0.f;
    }
    __syncthreads();

    for (int kt = 0; kt < NN / 64; kt++) {
        // load K (transposed) and V tiles
        const size_t base_k = (size_t)(b * NN + kt * 64) * C3 + CC + (size_t)h * DD;
        const size_t base_v = base_k + CC;
#pragma unroll
        for (int i = 0; i < 16; i++) {
            int e = tid + i * 256;
            int r = e >> 6, d = e & 63;
            Kt[d * SP + r] = g_qkv[base_k + (size_t)r * C3 + d];
            Vs[r * 64 + d] = g_qkv[base_v + (size_t)r * C3 + d];
        }
        __syncthreads();

        // S = scale * Q K^T  (rows ty*4+i, cols tx*4+j)
        float s[4][4];
#pragma unroll
        for (int i = 0; i < 4; i++)
#pragma unroll
            for (int j = 0; j < 4; j++) s[i][j] = 0.f;

#pragma unroll 4
        for (int d = 0; d < 64; d++) {
            float a[4];
#pragma unroll
            for (int i = 0; i < 4; i++) a[i] = Qs[(ty * 4 + i) * 64 + d];
            float4 b4 = *reinterpret_cast<const float4*>(&Kt[d * SP + tx * 4]);
            float bv[4] = {b4.x, b4.y, b4.z, b4.w};
#pragma unroll
            for (int i = 0; i < 4; i++)
#pragma unroll
                for (int j = 0; j < 4; j++) s[i][j] += a[i] * bv[j];
        }

        // online softmax per row (row owned by the 16 threads sharing ty)
#pragma unroll
        for (int i = 0; i < 4; i++) {
            float mx = -1e30f;
#pragma unroll
            for (int j = 0; j < 4; j++) {
                s[i][j] *= scale;
                mx = fmaxf(mx, s[i][j]);
            }
#pragma unroll
            for (int off = 8; off >= 1; off >>= 1)
                mx = fmaxf(mx, __shfl_xor_sync(0xffffffffu, mx, off));
            float mnew = fmaxf(m_i[i], mx);
            float rsum = 0.f;
#pragma unroll
            for (int j = 0; j < 4; j++) {
                float p = __expf(s[i][j] - mnew);
                s[i][j] = p;
                rsum += p;
            }
#pragma unroll
            for (int off = 8; off >= 1; off >>= 1)
                rsum += __shfl_xor_sync(0xffffffffu, rsum, off);
            float corr = __expf(m_i[i] - mnew);
            l_i[i] = l_i[i] * corr + rsum;
            m_i[i] = mnew;
#pragma unroll
            for (int j = 0; j < 4; j++) o_acc[i][j] *= corr;
            // stash P tile
            float4 p4 = make_float4(s[i][0], s[i][1], s[i][2], s[i][3]);
            *reinterpret_cast<float4*>(&Ps[(ty * 4 + i) * SP + tx * 4]) = p4;
        }
        __syncthreads();

        // O += P @ V  (O cols tx*4+j in d-space)
#pragma unroll 4
        for (int c = 0; c < 64; c++) {
            float pr[4];
#pragma unroll
            for (int i = 0; i < 4; i++) pr[i] = Ps[(ty * 4 + i) * SP + c];
            float4 v4 = *reinterpret_cast<const float4*>(&Vs[c * 64 + tx * 4]);
            float vv[4] = {v4.x, v4.y, v4.z, v4.w};
#pragma unroll
            for (int i = 0; i < 4; i++)
#pragma unroll
                for (int j = 0; j < 4; j++) o_acc[i][j] += pr[i] * vv[j];
        }
        __syncthreads();
    }

    // normalize and write to g_o in [B,N,C] layout
#pragma unroll
    for (int i = 0; i < 4; i++) {
        float inv = 1.0f / l_i[i];
        int n = qt * 64 + ty * 4 + i;
        size_t off = (size_t)(b * NN + n) * CC + (size_t)h * DD + tx * 4;
        float4 o4 = make_float4(o_acc[i][0] * inv, o_acc[i][1] * inv,
                                o_acc[i][2] * inv, o_acc[i][3] * inv);
        *reinterpret_cast<float4*>(&g_o[off]) = o4;
    }
}

// ----------------------------------------------------------------------------
extern "C" void kernel_launch(void* const* d_in, const int* in_sizes, int n_in,
                              void* d_out, int out_size) {
    const float* x      = (const float*)d_in[0];
    const float* w_qkv  = (const float*)d_in[1];
    const float* b_qkv  = (const float*)d_in[2];
    const float* gq     = (const float*)d_in[3];
    const float* gk     = (const float*)d_in[4];
    const float* w_proj = (const float*)d_in[5];
    const float* b_proj = (const float*)d_in[6];
    float* out = (float*)d_out;

    float* qkv_ptr = nullptr;
    float* o_ptr = nullptr;
    cudaGetSymbolAddress((void**)&qkv_ptr, g_qkv);
    cudaGetSymbolAddress((void**)&o_ptr, g_o);

    // 1) QKV GEMM: [8192,1024] @ [1024,3072]
    {
        dim3 grid(C3 / 64, MM / 64);
        gemm_bias_kernel<<<grid, 256>>>(x, w_qkv, b_qkv, qkv_ptr, MM, C3, CC);
    }

    // 2) head layernorm on q and k (in place)
    {
        int total_warps = 2 * MM * HH;          // 262144
        int blocks = total_warps / 8;           // 8 warps per 256-thread block
        qk_norm_kernel<<<blocks, 256>>>(gq, gk);
    }

    // 3) flash attention
    {
        int smem = (64 * 64 + 64 * SP + 64 * 64 + 64 * SP) * (int)sizeof(float); // 67584
        cudaFuncSetAttribute(flash_kernel, cudaFuncAttributeMaxDynamicSharedMemorySize, smem);
        dim3 grid(NN / 64, BB * HH);
        flash_kernel<<<grid, 256, smem>>>();
    }

    // 4) output projection: [8192,1024] @ [1024,1024]
    {
        dim3 grid(CC / 64, MM / 64);
        gemm_bias_kernel<<<grid, 256>>>(o_ptr, w_proj, b_proj, out, MM, CC, CC);
    }
}

// round 3
// speedup vs baseline: 1.0332x; 1.0332x over previous
#include <cuda_runtime.h>
#include <cstdint>
#include <math.h>

// Problem constants
#define BB 4
#define NN 2048
#define CC 1024
#define HH 16
#define DD 64
#define MM (BB * NN)          // 8192 rows
#define C3 (3 * CC)           // 3072
#define EPSV 1e-6f

// Scratch
__device__ float g_qkv[(size_t)MM * C3];       // 96 MB
__device__ float g_o[(size_t)MM * CC];         // 32 MB
__device__ float g_wqkvT[(size_t)C3 * CC];     // 12 MB  (w_qkv^T -> [3072][1024])
__device__ float g_wprojT[(size_t)CC * CC];    // 4 MB

__device__ __forceinline__ uint32_t f2tf32(float x) {
    uint32_t u;
    asm("cvt.rna.tf32.f32 %0, %1;" : "=r"(u) : "f"(x));
    return u;
}

// ---------------------------------------------------------------------------
// Weight transpose: in[R][Cn] -> out[Cn][R]
// ---------------------------------------------------------------------------
__global__ void transpose_kernel(const float* __restrict__ in, float* __restrict__ out,
                                 int R, int Cn) {
    __shared__ float t[32][33];
    int bx = blockIdx.x * 32, by = blockIdx.y * 32;
#pragma unroll
    for (int i = 0; i < 32; i += 8)
        t[threadIdx.y + i][threadIdx.x] = in[(size_t)(by + threadIdx.y + i) * Cn + bx + threadIdx.x];
    __syncthreads();
#pragma unroll
    for (int i = 0; i < 32; i += 8)
        out[(size_t)(bx + threadIdx.y + i) * R + by + threadIdx.x] = t[threadIdx.x][threadIdx.y + i];
}

// ---------------------------------------------------------------------------
// tf32 mma.sync GEMM: C[M,N] = A[M,K] @ BT[N,K]^T + bias[N]
// CTA tile 128x128, BK=32. 256 threads = 8 warps (2 m x 4 n), warp tile 64x32.
// mma.m16n8k8: 4 m-frags x 4 n-frags per warp.
// Smem stride 36 -> conflict-free fragment loads (bank = (4*row + k) % 32).
// ---------------------------------------------------------------------------
#define BKK 32
#define SSTR 36

__global__ void __launch_bounds__(256)
gemm_mma_kernel(const float* __restrict__ A, const float* __restrict__ BT,
                const float* __restrict__ bias, float* __restrict__ Cmat,
                int M, int N, int K) {
    __shared__ float As[128 * SSTR];
    __shared__ float Bs[128 * SSTR];

    const int tid = threadIdx.x;
    const int wid = tid >> 5;
    const int lane = tid & 31;
    const int gID = lane >> 2;     // 0..7
    const int tig = lane & 3;      // 0..3
    const int wm = (wid & 1) * 64;
    const int wn = (wid >> 1) * 32;
    const int bm = blockIdx.y * 128;
    const int bn = blockIdx.x * 128;

    // global load mapping: thread -> (row = tid/2, 16-float half = tid%2)
    const int lrow = tid >> 1;
    const int lcol = (tid & 1) * 16;
    const float* Ag = A + (size_t)(bm + lrow) * K + lcol;
    const float* Bg = BT + (size_t)(bn + lrow) * K + lcol;

    float acc[4][4][4];
#pragma unroll
    for (int mi = 0; mi < 4; mi++)
#pragma unroll
        for (int ni = 0; ni < 4; ni++)
#pragma unroll
            for (int r = 0; r < 4; r++) acc[mi][ni][r] = 0.f;

    float4 ra[4], rb[4];
#pragma unroll
    for (int i = 0; i < 4; i++) {
        ra[i] = *reinterpret_cast<const float4*>(Ag + i * 4);
        rb[i] = *reinterpret_cast<const float4*>(Bg + i * 4);
    }

    const int S = K / BKK;
    for (int s = 0; s < S; s++) {
        if (s) __syncthreads();
        // store prefetched tile to smem with tf32 rounding
#pragma unroll
        for (int i = 0; i < 4; i++) {
            uint4 ua, ub;
            ua.x = f2tf32(ra[i].x); ua.y = f2tf32(ra[i].y);
            ua.z = f2tf32(ra[i].z); ua.w = f2tf32(ra[i].w);
            ub.x = f2tf32(rb[i].x); ub.y = f2tf32(rb[i].y);
            ub.z = f2tf32(rb[i].z); ub.w = f2tf32(rb[i].w);
            *reinterpret_cast<uint4*>(&As[lrow * SSTR + lcol + i * 4]) = ua;
            *reinterpret_cast<uint4*>(&Bs[lrow * SSTR + lcol + i * 4]) = ub;
        }
        __syncthreads();

        if (s + 1 < S) {
            Ag += BKK; Bg += BKK;
#pragma unroll
            for (int i = 0; i < 4; i++) {
                ra[i] = *reinterpret_cast<const float4*>(Ag + i * 4);
                rb[i] = *reinterpret_cast<const float4*>(Bg + i * 4);
            }
        }

#pragma unroll
        for (int kk = 0; kk < 4; kk++) {
            const int k0 = kk * 8;
            uint32_t af[4][4], bf[4][2];
#pragma unroll
            for (int mi = 0; mi < 4; mi++) {
                int r0 = wm + mi * 16 + gID;
                af[mi][0] = __float_as_uint(As[r0 * SSTR + k0 + tig]);
                af[mi][1] = __float_as_uint(As[(r0 + 8) * SSTR + k0 + tig]);
                af[mi][2] = __float_as_uint(As[r0 * SSTR + k0 + tig + 4]);
                af[mi][3] = __float_as_uint(As[(r0 + 8) * SSTR + k0 + tig + 4]);
            }
#pragma unroll
            for (int ni = 0; ni < 4; ni++) {
                int n0 = wn + ni * 8 + gID;
                bf[ni][0] = __float_as_uint(Bs[n0 * SSTR + k0 + tig]);
                bf[ni][1] = __float_as_uint(Bs[n0 * SSTR + k0 + tig + 4]);
            }
#pragma unroll
            for (int mi = 0; mi < 4; mi++)
#pragma unroll
                for (int ni = 0; ni < 4; ni++) {
                    asm volatile(
                        "mma.sync.aligned.m16n8k8.row.col.f32.tf32.tf32.f32 "
                        "{%0,%1,%2,%3}, {%4,%5,%6,%7}, {%8,%9}, {%0,%1,%2,%3};"
                        : "+f"(acc[mi][ni][0]), "+f"(acc[mi][ni][1]),
                          "+f"(acc[mi][ni][2]), "+f"(acc[mi][ni][3])
                        : "r"(af[mi][0]), "r"(af[mi][1]), "r"(af[mi][2]), "r"(af[mi][3]),
                          "r"(bf[ni][0]), "r"(bf[ni][1]));
                }
        }
    }

    // epilogue: add bias, store
#pragma unroll
    for (int mi = 0; mi < 4; mi++) {
        int row0 = bm + wm + mi * 16 + gID;
#pragma unroll
        for (int ni = 0; ni < 4; ni++) {
            int col = bn + wn + ni * 8 + 2 * tig;
            float b0 = bias[col], b1 = bias[col + 1];
            float2 v0 = make_float2(acc[mi][ni][0] + b0, acc[mi][ni][1] + b1);
            float2 v1 = make_float2(acc[mi][ni][2] + b0, acc[mi][ni][3] + b1);
            *reinterpret_cast<float2*>(Cmat + (size_t)row0 * N + col) = v0;
            *reinterpret_cast<float2*>(Cmat + (size_t)(row0 + 8) * N + col) = v1;
        }
    }
}

// ----------------------------------------------------------------------------
// Head LayerNorm on q and k, in place inside g_qkv. One warp per (row, comp).
// ----------------------------------------------------------------------------
__global__ void qk_norm_kernel(const float* __restrict__ gamma_q,
                               const float* __restrict__ gamma_k) {
    int gwarp = (blockIdx.x * blockDim.x + threadIdx.x) >> 5;
    int lane = threadIdx.x & 31;
    int comp = gwarp & 1;
    int r = gwarp >> 1;
    int h = r & (HH - 1);
    int bn = r >> 4;

    float* ptr = g_qkv + (size_t)bn * C3 + comp * CC + h * DD;
    float2 v = *reinterpret_cast<float2*>(ptr + lane * 2);

    float s = v.x + v.y;
#pragma unroll
    for (int off = 16; off >= 1; off >>= 1) s += __shfl_xor_sync(0xffffffffu, s, off);
    float mu = s * (1.0f / 64.0f);

    float dx = v.x - mu, dy = v.y - mu;
    float e = dx * dx + dy * dy;
#pragma unroll
    for (int off = 16; off >= 1; off >>= 1) e += __shfl_xor_sync(0xffffffffu, e, off);
    float rs = rsqrtf(e * (1.0f / 64.0f) + EPSV);

    const float* gamma = comp ? gamma_k : gamma_q;
    float2 o;
    o.x = dx * rs * gamma[lane * 2 + 0];
    o.y = dy * rs * gamma[lane * 2 + 1];
    *reinterpret_cast<float2*>(ptr + lane * 2) = o;
}

// ----------------------------------------------------------------------------
// Flash attention fp32 (unchanged from passing R1 kernel)
// ----------------------------------------------------------------------------
#define SP 68
__global__ void flash_kernel() {
    extern __shared__ float smf[];
    float* Qs = smf;
    float* Kt = Qs + 64 * 64;
    float* Vs = Kt + 64 * SP;
    float* Ps = Vs + 64 * 64;

    const int tid = threadIdx.x;
    const int tx = tid & 15;
    const int ty = tid >> 4;
    const int qt = blockIdx.x;
    const int bh = blockIdx.y;
    const int b = bh >> 4;
    const int h = bh & 15;
    const float scale = 0.125f;

    const size_t base_q = (size_t)(b * NN + qt * 64) * C3 + (size_t)h * DD;
#pragma unroll
    for (int i = 0; i < 16; i++) {
        int e = tid + i * 256;
        int r = e >> 6, d = e & 63;
        Qs[r * 64 + d] = g_qkv[base_q + (size_t)r * C3 + d];
    }

    float m_i[4], l_i[4], o_acc[4][4];
#pragma unroll
    for (int i = 0; i < 4; i++) {
        m_i[i] = -1e30f; l_i[i] = 0.f;
#pragma unroll
        for (int j = 0; j < 4; j++) o_acc[i][j] = 0.f;
    }
    __syncthreads();

    for (int kt = 0; kt < NN / 64; kt++) {
        const size_t base_k = (size_t)(b * NN + kt * 64) * C3 + CC + (size_t)h * DD;
        const size_t base_v = base_k + CC;
#pragma unroll
        for (int i = 0; i < 16; i++) {
            int e = tid + i * 256;
            int r = e >> 6, d = e & 63;
            Kt[d * SP + r] = g_qkv[base_k + (size_t)r * C3 + d];
            Vs[r * 64 + d] = g_qkv[base_v + (size_t)r * C3 + d];
        }
        __syncthreads();

        float s[4][4];
#pragma unroll
        for (int i = 0; i < 4; i++)
#pragma unroll
            for (int j = 0; j < 4; j++) s[i][j] = 0.f;

#pragma unroll 4
        for (int d = 0; d < 64; d++) {
            float a[4];
#pragma unroll
            for (int i = 0; i < 4; i++) a[i] = Qs[(ty * 4 + i) * 64 + d];
            float4 b4 = *reinterpret_cast<const float4*>(&Kt[d * SP + tx * 4]);
            float bv[4] = {b4.x, b4.y, b4.z, b4.w};
#pragma unroll
            for (int i = 0; i < 4; i++)
#pragma unroll
                for (int j = 0; j < 4; j++) s[i][j] += a[i] * bv[j];
        }

#pragma unroll
        for (int i = 0; i < 4; i++) {
            float mx = -1e30f;
#pragma unroll
            for (int j = 0; j < 4; j++) { s[i][j] *= scale; mx = fmaxf(mx, s[i][j]); }
#pragma unroll
            for (int off = 8; off >= 1; off >>= 1)
                mx = fmaxf(mx, __shfl_xor_sync(0xffffffffu, mx, off));
            float mnew = fmaxf(m_i[i], mx);
            float rsum = 0.f;
#pragma unroll
            for (int j = 0; j < 4; j++) {
                float p = __expf(s[i][j] - mnew);
                s[i][j] = p; rsum += p;
            }
#pragma unroll
            for (int off = 8; off >= 1; off >>= 1)
                rsum += __shfl_xor_sync(0xffffffffu, rsum, off);
            float corr = __expf(m_i[i] - mnew);
            l_i[i] = l_i[i] * corr + rsum;
            m_i[i] = mnew;
#pragma unroll
            for (int j = 0; j < 4; j++) o_acc[i][j] *= corr;
            float4 p4 = make_float4(s[i][0], s[i][1], s[i][2], s[i][3]);
            *reinterpret_cast<float4*>(&Ps[(ty * 4 + i) * SP + tx * 4]) = p4;
        }
        __syncthreads();

#pragma unroll 4
        for (int c = 0; c < 64; c++) {
            float pr[4];
#pragma unroll
            for (int i = 0; i < 4; i++) pr[i] = Ps[(ty * 4 + i) * SP + c];
            float4 v4 = *reinterpret_cast<const float4*>(&Vs[c * 64 + tx * 4]);
            float vv[4] = {v4.x, v4.y, v4.z, v4.w};
#pragma unroll
            for (int i = 0; i < 4; i++)
#pragma unroll
                for (int j = 0; j < 4; j++) o_acc[i][j] += pr[i] * vv[j];
        }
        __syncthreads();
    }

#pragma unroll
    for (int i = 0; i < 4; i++) {
        float inv = 1.0f / l_i[i];
        int n = qt * 64 + ty * 4 + i;
        size_t off = (size_t)(b * NN + n) * CC + (size_t)h * DD + tx * 4;
        float4 o4 = make_float4(o_acc[i][0] * inv, o_acc[i][1] * inv,
                                o_acc[i][2] * inv, o_acc[i][3] * inv);
        *reinterpret_cast<float4*>(&g_o[off]) = o4;
    }
}

// ----------------------------------------------------------------------------
extern "C" void kernel_launch(void* const* d_in, const int* in_sizes, int n_in,
                              void* d_out, int out_size) {
    const float* x      = (const float*)d_in[0];
    const float* w_qkv  = (const float*)d_in[1];
    const float* b_qkv  = (const float*)d_in[2];
    const float* gq     = (const float*)d_in[3];
    const float* gk     = (const float*)d_in[4];
    const float* w_proj = (const float*)d_in[5];
    const float* b_proj = (const float*)d_in[6];
    float* out = (float*)d_out;

    float* qkv_ptr = nullptr; float* o_ptr = nullptr;
    float* wqkvT = nullptr; float* wprojT = nullptr;
    cudaGetSymbolAddress((void**)&qkv_ptr, g_qkv);
    cudaGetSymbolAddress((void**)&o_ptr, g_o);
    cudaGetSymbolAddress((void**)&wqkvT, g_wqkvT);
    cudaGetSymbolAddress((void**)&wprojT, g_wprojT);

    // 0) transpose weights to K-major for the B operand
    {
        dim3 blk(32, 8);
        transpose_kernel<<<dim3(C3 / 32, CC / 32), blk>>>(w_qkv, wqkvT, CC, C3);
        transpose_kernel<<<dim3(CC / 32, CC / 32), blk>>>(w_proj, wprojT, CC, CC);
    }

    // 1) QKV GEMM: [8192,1024] @ [1024,3072]
    {
        dim3 grid(C3 / 128, MM / 128);
        gemm_mma_kernel<<<grid, 256>>>(x, wqkvT, b_qkv, qkv_ptr, MM, C3, CC);
    }

    // 2) head layernorm on q and k (in place)
    {
        int total_warps = 2 * MM * HH;
        int blocks = total_warps / 8;
        qk_norm_kernel<<<blocks, 256>>>(gq, gk);
    }

    // 3) flash attention
    {
        int smem = (64 * 64 + 64 * SP + 64 * 64 + 64 * SP) * (int)sizeof(float);
        cudaFuncSetAttribute(flash_kernel, cudaFuncAttributeMaxDynamicSharedMemorySize, smem);
        dim3 grid(NN / 64, BB * HH);
        flash_kernel<<<grid, 256, smem>>>();
    }

    // 4) output projection: [8192,1024] @ [1024,1024]
    {
        dim3 grid(CC / 128, MM / 128);
        gemm_mma_kernel<<<grid, 256>>>(o_ptr, wprojT, b_proj, out, MM, CC, CC);
    }
}

// round 4
// speedup vs baseline: 3.2268x; 3.1231x over previous
#include <cuda_runtime.h>
#include <cstdint>
#include <math.h>

// Problem constants
#define BB 4
#define NN 2048
#define CC 1024
#define HH 16
#define DD 64
#define MM (BB * NN)          // 8192 rows
#define C3 (3 * CC)           // 3072
#define EPSV 1e-6f

// Scratch
__device__ float g_qkv[(size_t)MM * C3];       // 96 MB
__device__ float g_o[(size_t)MM * CC];         // 32 MB
__device__ float g_wqkvT[(size_t)C3 * CC];     // 12 MB
__device__ float g_wprojT[(size_t)CC * CC];    // 4 MB

__device__ __forceinline__ uint32_t f2tf32(float x) {
    uint32_t u;
    asm("cvt.rna.tf32.f32 %0, %1;" : "=r"(u) : "f"(x));
    return u;
}

#define MMA_TF32(c, a0, a1, a2, a3, b0, b1)                                   \
    asm volatile(                                                              \
        "mma.sync.aligned.m16n8k8.row.col.f32.tf32.tf32.f32 "                  \
        "{%0,%1,%2,%3}, {%4,%5,%6,%7}, {%8,%9}, {%0,%1,%2,%3};"                \
        : "+f"((c)[0]), "+f"((c)[1]), "+f"((c)[2]), "+f"((c)[3])               \
        : "r"(a0), "r"(a1), "r"(a2), "r"(a3), "r"(b0), "r"(b1))

// ---------------------------------------------------------------------------
// Weight transpose: in[R][Cn] -> out[Cn][R]
// ---------------------------------------------------------------------------
__global__ void transpose_kernel(const float* __restrict__ in, float* __restrict__ out,
                                 int R, int Cn) {
    __shared__ float t[32][33];
    int bx = blockIdx.x * 32, by = blockIdx.y * 32;
#pragma unroll
    for (int i = 0; i < 32; i += 8)
        t[threadIdx.y + i][threadIdx.x] = in[(size_t)(by + threadIdx.y + i) * Cn + bx + threadIdx.x];
    __syncthreads();
#pragma unroll
    for (int i = 0; i < 32; i += 8)
        out[(size_t)(bx + threadIdx.y + i) * R + by + threadIdx.x] = t[threadIdx.x][threadIdx.y + i];
}

// ---------------------------------------------------------------------------
// tf32 mma.sync GEMM: C[M,N] = A[M,K] @ BT[N,K]^T + bias[N]  (unchanged R3)
// ---------------------------------------------------------------------------
#define BKK 32
#define SSTR 36

__global__ void __launch_bounds__(256)
gemm_mma_kernel(const float* __restrict__ A, const float* __restrict__ BT,
                const float* __restrict__ bias, float* __restrict__ Cmat,
                int M, int N, int K) {
    __shared__ float As[128 * SSTR];
    __shared__ float Bs[128 * SSTR];

    const int tid = threadIdx.x;
    const int wid = tid >> 5;
    const int lane = tid & 31;
    const int gID = lane >> 2;
    const int tig = lane & 3;
    const int wm = (wid & 1) * 64;
    const int wn = (wid >> 1) * 32;
    const int bm = blockIdx.y * 128;
    const int bn = blockIdx.x * 128;

    const int lrow = tid >> 1;
    const int lcol = (tid & 1) * 16;
    const float* Ag = A + (size_t)(bm + lrow) * K + lcol;
    const float* Bg = BT + (size_t)(bn + lrow) * K + lcol;

    float acc[4][4][4];
#pragma unroll
    for (int mi = 0; mi < 4; mi++)
#pragma unroll
        for (int ni = 0; ni < 4; ni++)
#pragma unroll
            for (int r = 0; r < 4; r++) acc[mi][ni][r] = 0.f;

    float4 ra[4], rb[4];
#pragma unroll
    for (int i = 0; i < 4; i++) {
        ra[i] = *reinterpret_cast<const float4*>(Ag + i * 4);
        rb[i] = *reinterpret_cast<const float4*>(Bg + i * 4);
    }

    const int S = K / BKK;
    for (int s = 0; s < S; s++) {
        if (s) __syncthreads();
#pragma unroll
        for (int i = 0; i < 4; i++) {
            uint4 ua, ub;
            ua.x = f2tf32(ra[i].x); ua.y = f2tf32(ra[i].y);
            ua.z = f2tf32(ra[i].z); ua.w = f2tf32(ra[i].w);
            ub.x = f2tf32(rb[i].x); ub.y = f2tf32(rb[i].y);
            ub.z = f2tf32(rb[i].z); ub.w = f2tf32(rb[i].w);
            *reinterpret_cast<uint4*>(&As[lrow * SSTR + lcol + i * 4]) = ua;
            *reinterpret_cast<uint4*>(&Bs[lrow * SSTR + lcol + i * 4]) = ub;
        }
        __syncthreads();

        if (s + 1 < S) {
            Ag += BKK; Bg += BKK;
#pragma unroll
            for (int i = 0; i < 4; i++) {
                ra[i] = *reinterpret_cast<const float4*>(Ag + i * 4);
                rb[i] = *reinterpret_cast<const float4*>(Bg + i * 4);
            }
        }

#pragma unroll
        for (int kk = 0; kk < 4; kk++) {
            const int k0 = kk * 8;
            uint32_t af[4][4], bf[4][2];
#pragma unroll
            for (int mi = 0; mi < 4; mi++) {
                int r0 = wm + mi * 16 + gID;
                af[mi][0] = __float_as_uint(As[r0 * SSTR + k0 + tig]);
                af[mi][1] = __float_as_uint(As[(r0 + 8) * SSTR + k0 + tig]);
                af[mi][2] = __float_as_uint(As[r0 * SSTR + k0 + tig + 4]);
                af[mi][3] = __float_as_uint(As[(r0 + 8) * SSTR + k0 + tig + 4]);
            }
#pragma unroll
            for (int ni = 0; ni < 4; ni++) {
                int n0 = wn + ni * 8 + gID;
                bf[ni][0] = __float_as_uint(Bs[n0 * SSTR + k0 + tig]);
                bf[ni][1] = __float_as_uint(Bs[n0 * SSTR + k0 + tig + 4]);
            }
#pragma unroll
            for (int mi = 0; mi < 4; mi++)
#pragma unroll
                for (int ni = 0; ni < 4; ni++)
                    MMA_TF32(acc[mi][ni], af[mi][0], af[mi][1], af[mi][2], af[mi][3],
                             bf[ni][0], bf[ni][1]);
        }
    }

#pragma unroll
    for (int mi = 0; mi < 4; mi++) {
        int row0 = bm + wm + mi * 16 + gID;
#pragma unroll
        for (int ni = 0; ni < 4; ni++) {
            int col = bn + wn + ni * 8 + 2 * tig;
            float b0 = bias[col], b1 = bias[col + 1];
            float2 v0 = make_float2(acc[mi][ni][0] + b0, acc[mi][ni][1] + b1);
            float2 v1 = make_float2(acc[mi][ni][2] + b0, acc[mi][ni][3] + b1);
            *reinterpret_cast<float2*>(Cmat + (size_t)row0 * N + col) = v0;
            *reinterpret_cast<float2*>(Cmat + (size_t)(row0 + 8) * N + col) = v1;
        }
    }
}

// ----------------------------------------------------------------------------
// Head LayerNorm on q and k, in place. One warp per (row, comp).  (unchanged)
// ----------------------------------------------------------------------------
__global__ void qk_norm_kernel(const float* __restrict__ gamma_q,
                               const float* __restrict__ gamma_k) {
    int gwarp = (blockIdx.x * blockDim.x + threadIdx.x) >> 5;
    int lane = threadIdx.x & 31;
    int comp = gwarp & 1;
    int r = gwarp >> 1;
    int h = r & (HH - 1);
    int bn = r >> 4;

    float* ptr = g_qkv + (size_t)bn * C3 + comp * CC + h * DD;
    float2 v = *reinterpret_cast<float2*>(ptr + lane * 2);

    float s = v.x + v.y;
#pragma unroll
    for (int off = 16; off >= 1; off >>= 1) s += __shfl_xor_sync(0xffffffffu, s, off);
    float mu = s * (1.0f / 64.0f);

    float dx = v.x - mu, dy = v.y - mu;
    float e = dx * dx + dy * dy;
#pragma unroll
    for (int off = 16; off >= 1; off >>= 1) e += __shfl_xor_sync(0xffffffffu, e, off);
    float rs = rsqrtf(e * (1.0f / 64.0f) + EPSV);

    const float* gamma = comp ? gamma_k : gamma_q;
    float2 o;
    o.x = dx * rs * gamma[lane * 2 + 0];
    o.y = dy * rs * gamma[lane * 2 + 1];
    *reinterpret_cast<float2*>(ptr + lane * 2) = o;
}

// ----------------------------------------------------------------------------
// Flash attention with tf32 mma.sync.  CTA = 64 q rows, 4 warps, 128 threads.
// KV tile 64 rows.  Smem strides: Q/K/P 68 (banks 4g+t), V 72 (banks 8t+g).
// ----------------------------------------------------------------------------
#define QSTR 68
#define KSTR 68
#define VSTR 72
#define PSTR 68
#define FLASH_SMEM ((64 * QSTR + 64 * KSTR + 64 * VSTR + 64 * PSTR) * 4)

__global__ void __launch_bounds__(128, 3) flash_mma_kernel() {
    extern __shared__ uint32_t sm[];
    uint32_t* Qs = sm;
    uint32_t* Ks = Qs + 64 * QSTR;
    uint32_t* Vs = Ks + 64 * KSTR;
    uint32_t* Ps = Vs + 64 * VSTR;

    const int tid = threadIdx.x;
    const int wid = tid >> 5;
    const int lane = tid & 31;
    const int gID = lane >> 2;
    const int tig = lane & 3;
    const int qt = blockIdx.x;
    const int bh = blockIdx.y;
    const int b = bh >> 4;
    const int h = bh & 15;
    const int r0 = wid * 16;

    // load Q tile (scaled by D^-0.5 = 0.125, exact pow2), cvt tf32
    const size_t base_q = (size_t)(b * NN + qt * 64) * C3 + (size_t)h * DD;
#pragma unroll
    for (int i = 0; i < 8; i++) {
        int idx = tid + i * 128;
        int row = idx >> 4, c4 = (idx & 15) * 4;
        float4 v = *reinterpret_cast<const float4*>(&g_qkv[base_q + (size_t)row * C3 + c4]);
        uint4 u;
        u.x = f2tf32(v.x * 0.125f); u.y = f2tf32(v.y * 0.125f);
        u.z = f2tf32(v.z * 0.125f); u.w = f2tf32(v.w * 0.125f);
        *reinterpret_cast<uint4*>(&Qs[row * QSTR + c4]) = u;
    }

    float m0 = -1e30f, m1 = -1e30f, l0 = 0.f, l1 = 0.f;
    float o[8][4];
#pragma unroll
    for (int nf = 0; nf < 8; nf++)
#pragma unroll
        for (int j = 0; j < 4; j++) o[nf][j] = 0.f;

    for (int kt = 0; kt < NN / 64; kt++) {
        __syncthreads();   // prior-iteration K/V reads complete (covers Q on kt=0)
        const size_t base_k = (size_t)(b * NN + kt * 64) * C3 + CC + (size_t)h * DD;
        const size_t base_v = base_k + CC;
#pragma unroll
        for (int i = 0; i < 8; i++) {
            int idx = tid + i * 128;
            int row = idx >> 4, c4 = (idx & 15) * 4;
            float4 kv = *reinterpret_cast<const float4*>(&g_qkv[base_k + (size_t)row * C3 + c4]);
            uint4 uk;
            uk.x = f2tf32(kv.x); uk.y = f2tf32(kv.y);
            uk.z = f2tf32(kv.z); uk.w = f2tf32(kv.w);
            *reinterpret_cast<uint4*>(&Ks[row * KSTR + c4]) = uk;
            float4 vv = *reinterpret_cast<const float4*>(&g_qkv[base_v + (size_t)row * C3 + c4]);
            uint4 uv;
            uv.x = f2tf32(vv.x); uv.y = f2tf32(vv.y);
            uv.z = f2tf32(vv.z); uv.w = f2tf32(vv.w);
            *reinterpret_cast<uint4*>(&Vs[row * VSTR + c4]) = uv;
        }
        __syncthreads();

        // S = Q_scaled @ K^T
        float s[8][4];
#pragma unroll
        for (int nf = 0; nf < 8; nf++)
#pragma unroll
            for (int j = 0; j < 4; j++) s[nf][j] = 0.f;

#pragma unroll
        for (int kc = 0; kc < 8; kc++) {
            const int k0 = kc * 8;
            uint32_t a0 = Qs[(r0 + gID) * QSTR + k0 + tig];
            uint32_t a1 = Qs[(r0 + gID + 8) * QSTR + k0 + tig];
            uint32_t a2 = Qs[(r0 + gID) * QSTR + k0 + tig + 4];
            uint32_t a3 = Qs[(r0 + gID + 8) * QSTR + k0 + tig + 4];
#pragma unroll
            for (int nf = 0; nf < 8; nf++) {
                uint32_t b0 = Ks[(nf * 8 + gID) * KSTR + k0 + tig];
                uint32_t b1 = Ks[(nf * 8 + gID) * KSTR + k0 + tig + 4];
                MMA_TF32(s[nf], a0, a1, a2, a3, b0, b1);
            }
        }

        // online softmax: rows gID (c0,c1) and gID+8 (c2,c3)
        float mx0 = -1e30f, mx1 = -1e30f;
#pragma unroll
        for (int nf = 0; nf < 8; nf++) {
            mx0 = fmaxf(mx0, fmaxf(s[nf][0], s[nf][1]));
            mx1 = fmaxf(mx1, fmaxf(s[nf][2], s[nf][3]));
        }
        mx0 = fmaxf(mx0, __shfl_xor_sync(0xffffffffu, mx0, 1));
        mx0 = fmaxf(mx0, __shfl_xor_sync(0xffffffffu, mx0, 2));
        mx1 = fmaxf(mx1, __shfl_xor_sync(0xffffffffu, mx1, 1));
        mx1 = fmaxf(mx1, __shfl_xor_sync(0xffffffffu, mx1, 2));

        float mn0 = fmaxf(m0, mx0), mn1 = fmaxf(m1, mx1);
        float corr0 = __expf(m0 - mn0), corr1 = __expf(m1 - mn1);
        float rs0 = 0.f, rs1 = 0.f;
#pragma unroll
        for (int nf = 0; nf < 8; nf++) {
            s[nf][0] = __expf(s[nf][0] - mn0);
            s[nf][1] = __expf(s[nf][1] - mn0);
            s[nf][2] = __expf(s[nf][2] - mn1);
            s[nf][3] = __expf(s[nf][3] - mn1);
            rs0 += s[nf][0] + s[nf][1];
            rs1 += s[nf][2] + s[nf][3];
        }
        rs0 += __shfl_xor_sync(0xffffffffu, rs0, 1);
        rs0 += __shfl_xor_sync(0xffffffffu, rs0, 2);
        rs1 += __shfl_xor_sync(0xffffffffu, rs1, 1);
        rs1 += __shfl_xor_sync(0xffffffffu, rs1, 2);
        l0 = l0 * corr0 + rs0;
        l1 = l1 * corr1 + rs1;
        m0 = mn0; m1 = mn1;
#pragma unroll
        for (int nf = 0; nf < 8; nf++) {
            o[nf][0] *= corr0; o[nf][1] *= corr0;
            o[nf][2] *= corr1; o[nf][3] *= corr1;
        }

        // P -> smem (per-warp private rows), tf32
#pragma unroll
        for (int nf = 0; nf < 8; nf++) {
            uint2 p0 = make_uint2(f2tf32(s[nf][0]), f2tf32(s[nf][1]));
            uint2 p1 = make_uint2(f2tf32(s[nf][2]), f2tf32(s[nf][3]));
            *reinterpret_cast<uint2*>(&Ps[(r0 + gID) * PSTR + nf * 8 + 2 * tig]) = p0;
            *reinterpret_cast<uint2*>(&Ps[(r0 + gID + 8) * PSTR + nf * 8 + 2 * tig]) = p1;
        }
        __syncwarp();

        // O += P @ V
#pragma unroll
        for (int kc = 0; kc < 8; kc++) {
            const int k0 = kc * 8;
            uint32_t a0 = Ps[(r0 + gID) * PSTR + k0 + tig];
            uint32_t a1 = Ps[(r0 + gID + 8) * PSTR + k0 + tig];
            uint32_t a2 = Ps[(r0 + gID) * PSTR + k0 + tig + 4];
            uint32_t a3 = Ps[(r0 + gID + 8) * PSTR + k0 + tig + 4];
#pragma unroll
            for (int nf = 0; nf < 8; nf++) {
                uint32_t b0 = Vs[(k0 + tig) * VSTR + nf * 8 + gID];
                uint32_t b1 = Vs[(k0 + tig + 4) * VSTR + nf * 8 + gID];
                MMA_TF32(o[nf], a0, a1, a2, a3, b0, b1);
            }
        }
    }

    // normalize + store
    float inv0 = 1.0f / l0, inv1 = 1.0f / l1;
    int row0 = qt * 64 + r0 + gID;
#pragma unroll
    for (int nf = 0; nf < 8; nf++) {
        int col = h * DD + nf * 8 + 2 * tig;
        float2 v0 = make_float2(o[nf][0] * inv0, o[nf][1] * inv0);
        float2 v1 = make_float2(o[nf][2] * inv1, o[nf][3] * inv1);
        *reinterpret_cast<float2*>(&g_o[(size_t)(b * NN + row0) * CC + col]) = v0;
        *reinterpret_cast<float2*>(&g_o[(size_t)(b * NN + row0 + 8) * CC + col]) = v1;
    }
}

// ----------------------------------------------------------------------------
extern "C" void kernel_launch(void* const* d_in, const int* in_sizes, int n_in,
                              void* d_out, int out_size) {
    const float* x      = (const float*)d_in[0];
    const float* w_qkv  = (const float*)d_in[1];
    const float* b_qkv  = (const float*)d_in[2];
    const float* gq     = (const float*)d_in[3];
    const float* gk     = (const float*)d_in[4];
    const float* w_proj = (const float*)d_in[5];
    const float* b_proj = (const float*)d_in[6];
    float* out = (float*)d_out;

    float* qkv_ptr = nullptr; float* o_ptr = nullptr;
    float* wqkvT = nullptr; float* wprojT = nullptr;
    cudaGetSymbolAddress((void**)&qkv_ptr, g_qkv);
    cudaGetSymbolAddress((void**)&o_ptr, g_o);
    cudaGetSymbolAddress((void**)&wqkvT, g_wqkvT);
    cudaGetSymbolAddress((void**)&wprojT, g_wprojT);

    // 0) transpose weights to K-major
    {
        dim3 blk(32, 8);
        transpose_kernel<<<dim3(C3 / 32, CC / 32), blk>>>(w_qkv, wqkvT, CC, C3);
        transpose_kernel<<<dim3(CC / 32, CC / 32), blk>>>(w_proj, wprojT, CC, CC);
    }

    // 1) QKV GEMM
    {
        dim3 grid(C3 / 128, MM / 128);
        gemm_mma_kernel<<<grid, 256>>>(x, wqkvT, b_qkv, qkv_ptr, MM, C3, CC);
    }

    // 2) head layernorm on q and k
    {
        int total_warps = 2 * MM * HH;
        qk_norm_kernel<<<total_warps / 8, 256>>>(gq, gk);
    }

    // 3) flash attention (tf32 mma)
    {
        cudaFuncSetAttribute(flash_mma_kernel, cudaFuncAttributeMaxDynamicSharedMemorySize, FLASH_SMEM);
        dim3 grid(NN / 64, BB * HH);
        flash_mma_kernel<<<grid, 128, FLASH_SMEM>>>();
    }

    // 4) output projection
    {
        dim3 grid(CC / 128, MM / 128);
        gemm_mma_kernel<<<grid, 256>>>(o_ptr, wprojT, b_proj, out, MM, CC, CC);
    }
}

// round 5
// speedup vs baseline: 3.2454x; 1.0058x over previous
#include <cuda_runtime.h>
#include <cstdint>
#include <math.h>

// Problem constants
#define BB 4
#define NN 2048
#define CC 1024
#define HH 16
#define DD 64
#define MM (BB * NN)          // 8192 rows
#define C3 (3 * CC)           // 3072
#define EPSV 1e-6f

// Scratch
__device__ float g_qkv[(size_t)MM * C3];       // 96 MB
__device__ float g_o[(size_t)MM * CC];         // 32 MB
__device__ float g_wqkvT[(size_t)C3 * CC];     // 12 MB
__device__ float g_wprojT[(size_t)CC * CC];    // 4 MB

__device__ __forceinline__ uint32_t f2tf32(float x) {
    uint32_t u;
    asm("cvt.rna.tf32.f32 %0, %1;" : "=r"(u) : "f"(x));
    return u;
}

#define MMA_TF32(c, a0, a1, a2, a3, b0, b1)                                   \
    asm volatile(                                                              \
        "mma.sync.aligned.m16n8k8.row.col.f32.tf32.tf32.f32 "                  \
        "{%0,%1,%2,%3}, {%4,%5,%6,%7}, {%8,%9}, {%0,%1,%2,%3};"                \
        : "+f"((c)[0]), "+f"((c)[1]), "+f"((c)[2]), "+f"((c)[3])               \
        : "r"(a0), "r"(a1), "r"(a2), "r"(a3), "r"(b0), "r"(b1))

// ---------------------------------------------------------------------------
// Weight transpose: in[R][Cn] -> out[Cn][R]
// ---------------------------------------------------------------------------
__global__ void transpose_kernel(const float* __restrict__ in, float* __restrict__ out,
                                 int R, int Cn) {
    __shared__ float t[32][33];
    int bx = blockIdx.x * 32, by = blockIdx.y * 32;
#pragma unroll
    for (int i = 0; i < 32; i += 8)
        t[threadIdx.y + i][threadIdx.x] = in[(size_t)(by + threadIdx.y + i) * Cn + bx + threadIdx.x];
    __syncthreads();
#pragma unroll
    for (int i = 0; i < 32; i += 8)
        out[(size_t)(bx + threadIdx.y + i) * R + by + threadIdx.x] = t[threadIdx.x][threadIdx.y + i];
}

// ---------------------------------------------------------------------------
// tf32 mma.sync GEMM, double-buffered smem, 1 sync per BK step.
// C[M,N] = A[M,K] @ BT[N,K]^T + bias[N]
// CTA 128x128, BK=32, 8 warps (2m x 4n), warp tile 64x32.
// ---------------------------------------------------------------------------
#define BKK 32
#define SSTR 36
#define GEMM_BUF (128 * SSTR)
#define GEMM_SMEM (4 * GEMM_BUF * 4)   // 2 bufs x (As+Bs)

__global__ void __launch_bounds__(256)
gemm_mma_kernel(const float* __restrict__ A, const float* __restrict__ BT,
                const float* __restrict__ bias, float* __restrict__ Cmat,
                int M, int N, int K) {
    extern __shared__ float gsm[];
    // layout: As0, As1, Bs0, Bs1  (each GEMM_BUF floats)

    const int tid = threadIdx.x;
    const int wid = tid >> 5;
    const int lane = tid & 31;
    const int gID = lane >> 2;
    const int tig = lane & 3;
    const int wm = (wid & 1) * 64;
    const int wn = (wid >> 1) * 32;
    const int bm = blockIdx.y * 128;
    const int bn = blockIdx.x * 128;

    const int lrow = tid >> 1;
    const int lcol = (tid & 1) * 16;
    const float* Ag = A + (size_t)(bm + lrow) * K + lcol;
    const float* Bg = BT + (size_t)(bn + lrow) * K + lcol;

    float acc[4][4][4];
#pragma unroll
    for (int mi = 0; mi < 4; mi++)
#pragma unroll
        for (int ni = 0; ni < 4; ni++)
#pragma unroll
            for (int r = 0; r < 4; r++) acc[mi][ni][r] = 0.f;

    float4 ra[4], rb[4];
#pragma unroll
    for (int i = 0; i < 4; i++) {
        ra[i] = *reinterpret_cast<const float4*>(Ag + i * 4);
        rb[i] = *reinterpret_cast<const float4*>(Bg + i * 4);
    }

    // STS of stage 0 into buf 0
    {
        float* As = gsm;
        float* Bs = gsm + 2 * GEMM_BUF;
#pragma unroll
        for (int i = 0; i < 4; i++) {
            uint4 ua, ub;
            ua.x = f2tf32(ra[i].x); ua.y = f2tf32(ra[i].y);
            ua.z = f2tf32(ra[i].z); ua.w = f2tf32(ra[i].w);
            ub.x = f2tf32(rb[i].x); ub.y = f2tf32(rb[i].y);
            ub.z = f2tf32(rb[i].z); ub.w = f2tf32(rb[i].w);
            *reinterpret_cast<uint4*>(&As[lrow * SSTR + lcol + i * 4]) = ua;
            *reinterpret_cast<uint4*>(&Bs[lrow * SSTR + lcol + i * 4]) = ub;
        }
    }
    __syncthreads();

    const int S = K / BKK;
    for (int s = 0; s < S; s++) {
        const int buf = s & 1;
        float* As = gsm + buf * GEMM_BUF;
        float* Bs = gsm + 2 * GEMM_BUF + buf * GEMM_BUF;

        if (s + 1 < S) {
            Ag += BKK; Bg += BKK;
#pragma unroll
            for (int i = 0; i < 4; i++) {
                ra[i] = *reinterpret_cast<const float4*>(Ag + i * 4);
                rb[i] = *reinterpret_cast<const float4*>(Bg + i * 4);
            }
        }

#pragma unroll
        for (int kk = 0; kk < 4; kk++) {
            const int k0 = kk * 8;
            uint32_t af[4][4], bf[4][2];
#pragma unroll
            for (int mi = 0; mi < 4; mi++) {
                int r0 = wm + mi * 16 + gID;
                af[mi][0] = __float_as_uint(As[r0 * SSTR + k0 + tig]);
                af[mi][1] = __float_as_uint(As[(r0 + 8) * SSTR + k0 + tig]);
                af[mi][2] = __float_as_uint(As[r0 * SSTR + k0 + tig + 4]);
                af[mi][3] = __float_as_uint(As[(r0 + 8) * SSTR + k0 + tig + 4]);
            }
#pragma unroll
            for (int ni = 0; ni < 4; ni++) {
                int n0 = wn + ni * 8 + gID;
                bf[ni][0] = __float_as_uint(Bs[n0 * SSTR + k0 + tig]);
                bf[ni][1] = __float_as_uint(Bs[n0 * SSTR + k0 + tig + 4]);
            }
#pragma unroll
            for (int mi = 0; mi < 4; mi++)
#pragma unroll
                for (int ni = 0; ni < 4; ni++)
                    MMA_TF32(acc[mi][ni], af[mi][0], af[mi][1], af[mi][2], af[mi][3],
                             bf[ni][0], bf[ni][1]);
        }

        if (s + 1 < S) {
            float* Asn = gsm + (buf ^ 1) * GEMM_BUF;
            float* Bsn = gsm + 2 * GEMM_BUF + (buf ^ 1) * GEMM_BUF;
#pragma unroll
            for (int i = 0; i < 4; i++) {
                uint4 ua, ub;
                ua.x = f2tf32(ra[i].x); ua.y = f2tf32(ra[i].y);
                ua.z = f2tf32(ra[i].z); ua.w = f2tf32(ra[i].w);
                ub.x = f2tf32(rb[i].x); ub.y = f2tf32(rb[i].y);
                ub.z = f2tf32(rb[i].z); ub.w = f2tf32(rb[i].w);
                *reinterpret_cast<uint4*>(&Asn[lrow * SSTR + lcol + i * 4]) = ua;
                *reinterpret_cast<uint4*>(&Bsn[lrow * SSTR + lcol + i * 4]) = ub;
            }
            __syncthreads();
        }
    }

#pragma unroll
    for (int mi = 0; mi < 4; mi++) {
        int row0 = bm + wm + mi * 16 + gID;
#pragma unroll
        for (int ni = 0; ni < 4; ni++) {
            int col = bn + wn + ni * 8 + 2 * tig;
            float b0 = bias[col], b1 = bias[col + 1];
            float2 v0 = make_float2(acc[mi][ni][0] + b0, acc[mi][ni][1] + b1);
            float2 v1 = make_float2(acc[mi][ni][2] + b0, acc[mi][ni][3] + b1);
            *reinterpret_cast<float2*>(Cmat + (size_t)row0 * N + col) = v0;
            *reinterpret_cast<float2*>(Cmat + (size_t)(row0 + 8) * N + col) = v1;
        }
    }
}

// ----------------------------------------------------------------------------
// Head LayerNorm on q and k, in place. One warp per (row, comp).
// ----------------------------------------------------------------------------
__global__ void qk_norm_kernel(const float* __restrict__ gamma_q,
                               const float* __restrict__ gamma_k) {
    int gwarp = (blockIdx.x * blockDim.x + threadIdx.x) >> 5;
    int lane = threadIdx.x & 31;
    int comp = gwarp & 1;
    int r = gwarp >> 1;
    int h = r & (HH - 1);
    int bn = r >> 4;

    float* ptr = g_qkv + (size_t)bn * C3 + comp * CC + h * DD;
    float2 v = *reinterpret_cast<float2*>(ptr + lane * 2);

    float s = v.x + v.y;
#pragma unroll
    for (int off = 16; off >= 1; off >>= 1) s += __shfl_xor_sync(0xffffffffu, s, off);
    float mu = s * (1.0f / 64.0f);

    float dx = v.x - mu, dy = v.y - mu;
    float e = dx * dx + dy * dy;
#pragma unroll
    for (int off = 16; off >= 1; off >>= 1) e += __shfl_xor_sync(0xffffffffu, e, off);
    float rs = rsqrtf(e * (1.0f / 64.0f) + EPSV);

    const float* gamma = comp ? gamma_k : gamma_q;
    float2 o;
    o.x = dx * rs * gamma[lane * 2 + 0];
    o.y = dy * rs * gamma[lane * 2 + 1];
    *reinterpret_cast<float2*>(ptr + lane * 2) = o;
}

// ----------------------------------------------------------------------------
// Flash attention tf32 mma, v2: CTA = 128 q rows, 4 warps (32 q rows each,
// 2 m-frags), KV tile 64. Fragment reuse: K/V frags feed 2 MMAs each.
// ----------------------------------------------------------------------------
#define QSTR 68
#define KSTR 68
#define VSTR 72
#define PSTR 68
#define FLASH_SMEM ((128 * QSTR + 64 * KSTR + 64 * VSTR + 128 * PSTR) * 4)

__global__ void __launch_bounds__(128) flash_mma_kernel() {
    extern __shared__ uint32_t sm[];
    uint32_t* Qs = sm;                       // 128 x QSTR
    uint32_t* Ks = Qs + 128 * QSTR;          // 64 x KSTR
    uint32_t* Vs = Ks + 64 * KSTR;           // 64 x VSTR
    uint32_t* Ps = Vs + 64 * VSTR;           // 128 x PSTR

    const int tid = threadIdx.x;
    const int wid = tid >> 5;
    const int lane = tid & 31;
    const int gID = lane >> 2;
    const int tig = lane & 3;
    const int qt = blockIdx.x;               // 0..15 (128-row q tiles)
    const int bh = blockIdx.y;
    const int b = bh >> 4;
    const int h = bh & 15;
    const int wq0 = wid * 32;                // warp's first q row (2 m-frags)

    // load Q tile (128 rows), scaled by 0.125, cvt tf32
    const size_t base_q = (size_t)(b * NN + qt * 128) * C3 + (size_t)h * DD;
#pragma unroll
    for (int i = 0; i < 16; i++) {
        int idx = tid + i * 128;
        int row = idx >> 4, c4 = (idx & 15) * 4;
        float4 v = *reinterpret_cast<const float4*>(&g_qkv[base_q + (size_t)row * C3 + c4]);
        uint4 u;
        u.x = f2tf32(v.x * 0.125f); u.y = f2tf32(v.y * 0.125f);
        u.z = f2tf32(v.z * 0.125f); u.w = f2tf32(v.w * 0.125f);
        *reinterpret_cast<uint4*>(&Qs[row * QSTR + c4]) = u;
    }

    float m[2][2], l[2][2];
    float o[2][8][4];
#pragma unroll
    for (int mi = 0; mi < 2; mi++) {
        m[mi][0] = -1e30f; m[mi][1] = -1e30f;
        l[mi][0] = 0.f; l[mi][1] = 0.f;
#pragma unroll
        for (int nf = 0; nf < 8; nf++)
#pragma unroll
            for (int j = 0; j < 4; j++) o[mi][nf][j] = 0.f;
    }

    for (int kt = 0; kt < NN / 64; kt++) {
        __syncthreads();   // prior-iter K/V reads complete (covers Q stores on kt=0)
        const size_t base_k = (size_t)(b * NN + kt * 64) * C3 + CC + (size_t)h * DD;
        const size_t base_v = base_k + CC;
#pragma unroll
        for (int i = 0; i < 8; i++) {
            int idx = tid + i * 128;
            int row = idx >> 4, c4 = (idx & 15) * 4;
            float4 kv = *reinterpret_cast<const float4*>(&g_qkv[base_k + (size_t)row * C3 + c4]);
            uint4 uk;
            uk.x = f2tf32(kv.x); uk.y = f2tf32(kv.y);
            uk.z = f2tf32(kv.z); uk.w = f2tf32(kv.w);
            *reinterpret_cast<uint4*>(&Ks[row * KSTR + c4]) = uk;
            float4 vv = *reinterpret_cast<const float4*>(&g_qkv[base_v + (size_t)row * C3 + c4]);
            uint4 uv;
            uv.x = f2tf32(vv.x); uv.y = f2tf32(vv.y);
            uv.z = f2tf32(vv.z); uv.w = f2tf32(vv.w);
            *reinterpret_cast<uint4*>(&Vs[row * VSTR + c4]) = uv;
        }
        __syncthreads();

        // S = Q_scaled @ K^T   (2 m-frags x 8 n-frags)
        float s[2][8][4];
#pragma unroll
        for (int mi = 0; mi < 2; mi++)
#pragma unroll
            for (int nf = 0; nf < 8; nf++)
#pragma unroll
                for (int j = 0; j < 4; j++) s[mi][nf][j] = 0.f;

#pragma unroll
        for (int kc = 0; kc < 8; kc++) {
            const int k0 = kc * 8;
            uint32_t a[2][4];
#pragma unroll
            for (int mi = 0; mi < 2; mi++) {
                int rr = wq0 + mi * 16;
                a[mi][0] = Qs[(rr + gID) * QSTR + k0 + tig];
                a[mi][1] = Qs[(rr + gID + 8) * QSTR + k0 + tig];
                a[mi][2] = Qs[(rr + gID) * QSTR + k0 + tig + 4];
                a[mi][3] = Qs[(rr + gID + 8) * QSTR + k0 + tig + 4];
            }
#pragma unroll
            for (int nf = 0; nf < 8; nf++) {
                uint32_t b0 = Ks[(nf * 8 + gID) * KSTR + k0 + tig];
                uint32_t b1 = Ks[(nf * 8 + gID) * KSTR + k0 + tig + 4];
                MMA_TF32(s[0][nf], a[0][0], a[0][1], a[0][2], a[0][3], b0, b1);
                MMA_TF32(s[1][nf], a[1][0], a[1][1], a[1][2], a[1][3], b0, b1);
            }
        }

        // online softmax per m-frag: rows gID (c0,c1) and gID+8 (c2,c3)
#pragma unroll
        for (int mi = 0; mi < 2; mi++) {
            float mx0 = -1e30f, mx1 = -1e30f;
#pragma unroll
            for (int nf = 0; nf < 8; nf++) {
                mx0 = fmaxf(mx0, fmaxf(s[mi][nf][0], s[mi][nf][1]));
                mx1 = fmaxf(mx1, fmaxf(s[mi][nf][2], s[mi][nf][3]));
            }
            mx0 = fmaxf(mx0, __shfl_xor_sync(0xffffffffu, mx0, 1));
            mx0 = fmaxf(mx0, __shfl_xor_sync(0xffffffffu, mx0, 2));
            mx1 = fmaxf(mx1, __shfl_xor_sync(0xffffffffu, mx1, 1));
            mx1 = fmaxf(mx1, __shfl_xor_sync(0xffffffffu, mx1, 2));

            float mn0 = fmaxf(m[mi][0], mx0), mn1 = fmaxf(m[mi][1], mx1);
            float corr0 = __expf(m[mi][0] - mn0), corr1 = __expf(m[mi][1] - mn1);
            float rs0 = 0.f, rs1 = 0.f;
#pragma unroll
            for (int nf = 0; nf < 8; nf++) {
                s[mi][nf][0] = __expf(s[mi][nf][0] - mn0);
                s[mi][nf][1] = __expf(s[mi][nf][1] - mn0);
                s[mi][nf][2] = __expf(s[mi][nf][2] - mn1);
                s[mi][nf][3] = __expf(s[mi][nf][3] - mn1);
                rs0 += s[mi][nf][0] + s[mi][nf][1];
                rs1 += s[mi][nf][2] + s[mi][nf][3];
            }
            rs0 += __shfl_xor_sync(0xffffffffu, rs0, 1);
            rs0 += __shfl_xor_sync(0xffffffffu, rs0, 2);
            rs1 += __shfl_xor_sync(0xffffffffu, rs1, 1);
            rs1 += __shfl_xor_sync(0xffffffffu, rs1, 2);
            l[mi][0] = l[mi][0] * corr0 + rs0;
            l[mi][1] = l[mi][1] * corr1 + rs1;
            m[mi][0] = mn0; m[mi][1] = mn1;
#pragma unroll
            for (int nf = 0; nf < 8; nf++) {
                o[mi][nf][0] *= corr0; o[mi][nf][1] *= corr0;
                o[mi][nf][2] *= corr1; o[mi][nf][3] *= corr1;
            }

            // P -> smem (per-warp private rows), tf32
            int rr = wq0 + mi * 16;
#pragma unroll
            for (int nf = 0; nf < 8; nf++) {
                uint2 p0 = make_uint2(f2tf32(s[mi][nf][0]), f2tf32(s[mi][nf][1]));
                uint2 p1 = make_uint2(f2tf32(s[mi][nf][2]), f2tf32(s[mi][nf][3]));
                *reinterpret_cast<uint2*>(&Ps[(rr + gID) * PSTR + nf * 8 + 2 * tig]) = p0;
                *reinterpret_cast<uint2*>(&Ps[(rr + gID + 8) * PSTR + nf * 8 + 2 * tig]) = p1;
            }
        }
        __syncwarp();

        // O += P @ V
#pragma unroll
        for (int kc = 0; kc < 8; kc++) {
            const int k0 = kc * 8;
            uint32_t a[2][4];
#pragma unroll
            for (int mi = 0; mi < 2; mi++) {
                int rr = wq0 + mi * 16;
                a[mi][0] = Ps[(rr + gID) * PSTR + k0 + tig];
                a[mi][1] = Ps[(rr + gID + 8) * PSTR + k0 + tig];
                a[mi][2] = Ps[(rr + gID) * PSTR + k0 + tig + 4];
                a[mi][3] = Ps[(rr + gID + 8) * PSTR + k0 + tig + 4];
            }
#pragma unroll
            for (int nf = 0; nf < 8; nf++) {
                uint32_t b0 = Vs[(k0 + tig) * VSTR + nf * 8 + gID];
                uint32_t b1 = Vs[(k0 + tig + 4) * VSTR + nf * 8 + gID];
                MMA_TF32(o[0][nf], a[0][0], a[0][1], a[0][2], a[0][3], b0, b1);
                MMA_TF32(o[1][nf], a[1][0], a[1][1], a[1][2], a[1][3], b0, b1);
            }
        }
    }

    // normalize + store
#pragma unroll
    for (int mi = 0; mi < 2; mi++) {
        float inv0 = 1.0f / l[mi][0], inv1 = 1.0f / l[mi][1];
        int row0 = qt * 128 + wq0 + mi * 16 + gID;
#pragma unroll
        for (int nf = 0; nf < 8; nf++) {
            int col = h * DD + nf * 8 + 2 * tig;
            float2 v0 = make_float2(o[mi][nf][0] * inv0, o[mi][nf][1] * inv0);
            float2 v1 = make_float2(o[mi][nf][2] * inv1, o[mi][nf][3] * inv1);
            *reinterpret_cast<float2*>(&g_o[(size_t)(b * NN + row0) * CC + col]) = v0;
            *reinterpret_cast<float2*>(&g_o[(size_t)(b * NN + row0 + 8) * CC + col]) = v1;
        }
    }
}

// ----------------------------------------------------------------------------
extern "C" void kernel_launch(void* const* d_in, const int* in_sizes, int n_in,
                              void* d_out, int out_size) {
    const float* x      = (const float*)d_in[0];
    const float* w_qkv  = (const float*)d_in[1];
    const float* b_qkv  = (const float*)d_in[2];
    const float* gq     = (const float*)d_in[3];
    const float* gk     = (const float*)d_in[4];
    const float* w_proj = (const float*)d_in[5];
    const float* b_proj = (const float*)d_in[6];
    float* out = (float*)d_out;

    float* qkv_ptr = nullptr; float* o_ptr = nullptr;
    float* wqkvT = nullptr; float* wprojT = nullptr;
    cudaGetSymbolAddress((void**)&qkv_ptr, g_qkv);
    cudaGetSymbolAddress((void**)&o_ptr, g_o);
    cudaGetSymbolAddress((void**)&wqkvT, g_wqkvT);
    cudaGetSymbolAddress((void**)&wprojT, g_wprojT);

    // 0) transpose weights to K-major
    {
        dim3 blk(32, 8);
        transpose_kernel<<<dim3(C3 / 32, CC / 32), blk>>>(w_qkv, wqkvT, CC, C3);
        transpose_kernel<<<dim3(CC / 32, CC / 32), blk>>>(w_proj, wprojT, CC, CC);
    }

    cudaFuncSetAttribute(gemm_mma_kernel, cudaFuncAttributeMaxDynamicSharedMemorySize, GEMM_SMEM);

    // 1) QKV GEMM
    {
        dim3 grid(C3 / 128, MM / 128);
        gemm_mma_kernel<<<grid, 256, GEMM_SMEM>>>(x, wqkvT, b_qkv, qkv_ptr, MM, C3, CC);
    }

    // 2) head layernorm on q and k
    {
        int total_warps = 2 * MM * HH;
        qk_norm_kernel<<<total_warps / 8, 256>>>(gq, gk);
    }

    // 3) flash attention (tf32 mma, 128 q rows / CTA)
    {
        cudaFuncSetAttribute(flash_mma_kernel, cudaFuncAttributeMaxDynamicSharedMemorySize, FLASH_SMEM);
        dim3 grid(NN / 128, BB * HH);
        flash_mma_kernel<<<grid, 128, FLASH_SMEM>>>();
    }

    // 4) output projection
    {
        dim3 grid(CC / 128, MM / 128);
        gemm_mma_kernel<<<grid, 256, GEMM_SMEM>>>(o_ptr, wprojT, b_proj, out, MM, CC, CC);
    }
}

// round 8
// speedup vs baseline: 4.4746x; 1.3788x over previous
#include <cuda_runtime.h>
#include <cuda_fp16.h>
#include <cstdint>
#include <math.h>

// Problem constants
#define BB 4
#define NN 2048
#define CC 1024
#define HH 16
#define DD 64
#define MM (BB * NN)          // 8192
#define C3 (3 * CC)           // 3072
#define EPSV 1e-6f

// Scratch (16B-aligned for vectorized access)
__device__ __align__(16) float  g_qkv[(size_t)MM * C3];       // 96 MB
__device__ __align__(16) float  g_o[(size_t)MM * CC];         // 32 MB
__device__ __align__(16) __half g_xh[(size_t)MM * CC];        // 16 MB
__device__ __align__(16) __half g_oh[(size_t)MM * CC];        // 16 MB
__device__ __align__(16) __half g_wqkvTh[(size_t)C3 * CC];    // 6 MB
__device__ __align__(16) __half g_wprojTh[(size_t)CC * CC];   // 2 MB

__device__ __forceinline__ uint32_t f2tf32(float x) {
    uint32_t u;
    asm("cvt.rna.tf32.f32 %0, %1;" : "=r"(u) : "f"(x));
    return u;
}
__device__ __forceinline__ uint32_t f2h2(float lo, float hi) {
    __half2 h = __float22half2_rn(make_float2(lo, hi));
    return *reinterpret_cast<uint32_t*>(&h);
}

#define MMA_TF32(c, a0, a1, a2, a3, b0, b1)                                   \
    asm volatile(                                                              \
        "mma.sync.aligned.m16n8k8.row.col.f32.tf32.tf32.f32 "                  \
        "{%0,%1,%2,%3}, {%4,%5,%6,%7}, {%8,%9}, {%0,%1,%2,%3};"                \
        : "+f"((c)[0]), "+f"((c)[1]), "+f"((c)[2]), "+f"((c)[3])               \
        : "r"(a0), "r"(a1), "r"(a2), "r"(a3), "r"(b0), "r"(b1))

#define MMA_F16(c, a0, a1, a2, a3, b0, b1)                                     \
    asm volatile(                                                               \
        "mma.sync.aligned.m16n8k16.row.col.f32.f16.f16.f32 "                    \
        "{%0,%1,%2,%3}, {%4,%5,%6,%7}, {%8,%9}, {%0,%1,%2,%3};"                 \
        : "+f"((c)[0]), "+f"((c)[1]), "+f"((c)[2]), "+f"((c)[3])                \
        : "r"(a0), "r"(a1), "r"(a2), "r"(a3), "r"(b0), "r"(b1))

// ---------------------------------------------------------------------------
// Weight transpose + fp16 convert: in[R][Cn] f32 -> out[Cn][R] fp16
// ---------------------------------------------------------------------------
__global__ void transpose_h_kernel(const float* __restrict__ in, __half* __restrict__ out,
                                   int R, int Cn) {
    __shared__ float t[32][33];
    int bx = blockIdx.x * 32, by = blockIdx.y * 32;
#pragma unroll
    for (int i = 0; i < 32; i += 8)
        t[threadIdx.y + i][threadIdx.x] = in[(size_t)(by + threadIdx.y + i) * Cn + bx + threadIdx.x];
    __syncthreads();
#pragma unroll
    for (int i = 0; i < 32; i += 8)
        out[(size_t)(bx + threadIdx.y + i) * R + by + threadIdx.x] =
            __float2half(t[threadIdx.x][threadIdx.y + i]);
}

// ---------------------------------------------------------------------------
// f32 -> fp16 bulk convert (8 elems/thread)
// ---------------------------------------------------------------------------
__global__ void hconv_kernel(const float* __restrict__ src, __half* __restrict__ dst) {
    size_t i = (size_t)blockIdx.x * blockDim.x + threadIdx.x;   // one per 8 elems
    const float4* p = reinterpret_cast<const float4*>(src) + 2 * i;
    float4 a = p[0], b = p[1];
    uint4 u;
    u.x = f2h2(a.x, a.y); u.y = f2h2(a.z, a.w);
    u.z = f2h2(b.x, b.y); u.w = f2h2(b.z, b.w);
    reinterpret_cast<uint4*>(dst)[i] = u;
}

// ---------------------------------------------------------------------------
// fp16 mma.sync GEMM: C[M,N] = Ah[M,K] @ BTh[N,K]^T + bias[N]
// CTA 128x128, BK=32, 8 warps (2m x 4n), warp tile 64x32, m16n8k16,
// double-buffered smem (u32-packed fp16, row stride 20 u32).
// Each thread loads 2 x uint4 (= 16 halves) so the full 32-half row is
// covered by 2 threads.  (R7 bug: only 1 uint4 -> half the tile unwritten.)
// ---------------------------------------------------------------------------
#define GSTR 20

__global__ void __launch_bounds__(256)
gemm_h_kernel(const __half* __restrict__ Ah, const __half* __restrict__ BTh,
              const float* __restrict__ bias, float* __restrict__ Cmat,
              int M, int N, int K) {
    __shared__ uint32_t As2[2][128 * GSTR];
    __shared__ uint32_t Bs2[2][128 * GSTR];

    const int tid = threadIdx.x;
    const int wid = tid >> 5;
    const int lane = tid & 31;
    const int gID = lane >> 2;
    const int tig = lane & 3;
    const int wm = (wid & 1) * 64;
    const int wn = (wid >> 1) * 32;
    const int bm = blockIdx.y * 128;
    const int bn = blockIdx.x * 128;

    const int lrow = tid >> 1;
    const int lhalf = (tid & 1) * 8;       // u32 offset in row (0 or 8)
    const __half* Agp = Ah + (size_t)(bm + lrow) * K + (tid & 1) * 16;
    const __half* Bgp = BTh + (size_t)(bn + lrow) * K + (tid & 1) * 16;

    float acc[4][4][4];
#pragma unroll
    for (int mi = 0; mi < 4; mi++)
#pragma unroll
        for (int ni = 0; ni < 4; ni++)
#pragma unroll
            for (int r = 0; r < 4; r++) acc[mi][ni][r] = 0.f;

    uint4 rA0 = *reinterpret_cast<const uint4*>(Agp);
    uint4 rA1 = *reinterpret_cast<const uint4*>(Agp + 8);
    uint4 rB0 = *reinterpret_cast<const uint4*>(Bgp);
    uint4 rB1 = *reinterpret_cast<const uint4*>(Bgp + 8);
    *reinterpret_cast<uint4*>(&As2[0][lrow * GSTR + lhalf]) = rA0;
    *reinterpret_cast<uint4*>(&As2[0][lrow * GSTR + lhalf + 4]) = rA1;
    *reinterpret_cast<uint4*>(&Bs2[0][lrow * GSTR + lhalf]) = rB0;
    *reinterpret_cast<uint4*>(&Bs2[0][lrow * GSTR + lhalf + 4]) = rB1;
    __syncthreads();

    const int S = K / 32;
    for (int s = 0; s < S; s++) {
        const int buf = s & 1;
        if (s + 1 < S) {
            Agp += 32; Bgp += 32;
            rA0 = *reinterpret_cast<const uint4*>(Agp);
            rA1 = *reinterpret_cast<const uint4*>(Agp + 8);
            rB0 = *reinterpret_cast<const uint4*>(Bgp);
            rB1 = *reinterpret_cast<const uint4*>(Bgp + 8);
        }

#pragma unroll
        for (int j = 0; j < 2; j++) {
            const int k2 = j * 8;
            uint32_t af[4][4], bf[4][2];
#pragma unroll
            for (int mi = 0; mi < 4; mi++) {
                int r0 = wm + mi * 16 + gID;
                af[mi][0] = As2[buf][r0 * GSTR + k2 + tig];
                af[mi][1] = As2[buf][(r0 + 8) * GSTR + k2 + tig];
                af[mi][2] = As2[buf][r0 * GSTR + k2 + tig + 4];
                af[mi][3] = As2[buf][(r0 + 8) * GSTR + k2 + tig + 4];
            }
#pragma unroll
            for (int ni = 0; ni < 4; ni++) {
                int n0 = wn + ni * 8 + gID;
                bf[ni][0] = Bs2[buf][n0 * GSTR + k2 + tig];
                bf[ni][1] = Bs2[buf][n0 * GSTR + k2 + tig + 4];
            }
#pragma unroll
            for (int mi = 0; mi < 4; mi++)
#pragma unroll
                for (int ni = 0; ni < 4; ni++)
                    MMA_F16(acc[mi][ni], af[mi][0], af[mi][1], af[mi][2], af[mi][3],
                            bf[ni][0], bf[ni][1]);
        }

        if (s + 1 < S) {
            *reinterpret_cast<uint4*>(&As2[buf ^ 1][lrow * GSTR + lhalf]) = rA0;
            *reinterpret_cast<uint4*>(&As2[buf ^ 1][lrow * GSTR + lhalf + 4]) = rA1;
            *reinterpret_cast<uint4*>(&Bs2[buf ^ 1][lrow * GSTR + lhalf]) = rB0;
            *reinterpret_cast<uint4*>(&Bs2[buf ^ 1][lrow * GSTR + lhalf + 4]) = rB1;
            __syncthreads();
        }
    }

#pragma unroll
    for (int mi = 0; mi < 4; mi++) {
        int row0 = bm + wm + mi * 16 + gID;
#pragma unroll
        for (int ni = 0; ni < 4; ni++) {
            int col = bn + wn + ni * 8 + 2 * tig;
            float b0 = bias[col], b1 = bias[col + 1];
            float2 v0 = make_float2(acc[mi][ni][0] + b0, acc[mi][ni][1] + b1);
            float2 v1 = make_float2(acc[mi][ni][2] + b0, acc[mi][ni][3] + b1);
            *reinterpret_cast<float2*>(Cmat + (size_t)row0 * N + col) = v0;
            *reinterpret_cast<float2*>(Cmat + (size_t)(row0 + 8) * N + col) = v1;
        }
    }
}

// ----------------------------------------------------------------------------
// Head LayerNorm on q and k, in place in g_qkv. One warp per (row, comp).
// (R5 exact)
// ----------------------------------------------------------------------------
__global__ void qk_norm_kernel(const float* __restrict__ gamma_q,
                               const float* __restrict__ gamma_k) {
    int gwarp = (blockIdx.x * blockDim.x + threadIdx.x) >> 5;
    int lane = threadIdx.x & 31;
    int comp = gwarp & 1;
    int r = gwarp >> 1;
    int h = r & (HH - 1);
    int bn = r >> 4;

    float* ptr = g_qkv + (size_t)bn * C3 + comp * CC + h * DD;
    float2 v = *reinterpret_cast<float2*>(ptr + lane * 2);

    float s = v.x + v.y;
#pragma unroll
    for (int off = 16; off >= 1; off >>= 1) s += __shfl_xor_sync(0xffffffffu, s, off);
    float mu = s * (1.0f / 64.0f);

    float dx = v.x - mu, dy = v.y - mu;
    float e = dx * dx + dy * dy;
#pragma unroll
    for (int off = 16; off >= 1; off >>= 1) e += __shfl_xor_sync(0xffffffffu, e, off);
    float rs = rsqrtf(e * (1.0f / 64.0f) + EPSV);

    const float* gamma = comp ? gamma_k : gamma_q;
    float2 o;
    o.x = dx * rs * gamma[lane * 2 + 0];
    o.y = dy * rs * gamma[lane * 2 + 1];
    *reinterpret_cast<float2*>(ptr + lane * 2) = o;
}

// ----------------------------------------------------------------------------
// Flash attention tf32 mma (R5 exact): CTA = 128 q rows, 4 warps, KV tile 64.
// ----------------------------------------------------------------------------
#define QSTR 68
#define KSTR 68
#define VSTR 72
#define PSTR 68
#define FLASH_SMEM ((128 * QSTR + 64 * KSTR + 64 * VSTR + 128 * PSTR) * 4)

__global__ void __launch_bounds__(128) flash_mma_kernel() {
    extern __shared__ uint32_t sm[];
    uint32_t* Qs = sm;
    uint32_t* Ks = Qs + 128 * QSTR;
    uint32_t* Vs = Ks + 64 * KSTR;
    uint32_t* Ps = Vs + 64 * VSTR;

    const int tid = threadIdx.x;
    const int wid = tid >> 5;
    const int lane = tid & 31;
    const int gID = lane >> 2;
    const int tig = lane & 3;
    const int qt = blockIdx.x;
    const int bh = blockIdx.y;
    const int b = bh >> 4;
    const int h = bh & 15;
    const int wq0 = wid * 32;

    const size_t base_q = (size_t)(b * NN + qt * 128) * C3 + (size_t)h * DD;
#pragma unroll
    for (int i = 0; i < 16; i++) {
        int idx = tid + i * 128;
        int row = idx >> 4, c4 = (idx & 15) * 4;
        float4 v = *reinterpret_cast<const float4*>(&g_qkv[base_q + (size_t)row * C3 + c4]);
        uint4 u;
        u.x = f2tf32(v.x * 0.125f); u.y = f2tf32(v.y * 0.125f);
        u.z = f2tf32(v.z * 0.125f); u.w = f2tf32(v.w * 0.125f);
        *reinterpret_cast<uint4*>(&Qs[row * QSTR + c4]) = u;
    }

    float m[2][2], l[2][2], o[2][8][4];
#pragma unroll
    for (int mi = 0; mi < 2; mi++) {
        m[mi][0] = -1e30f; m[mi][1] = -1e30f;
        l[mi][0] = 0.f; l[mi][1] = 0.f;
#pragma unroll
        for (int nf = 0; nf < 8; nf++)
#pragma unroll
            for (int j = 0; j < 4; j++) o[mi][nf][j] = 0.f;
    }

    for (int kt = 0; kt < NN / 64; kt++) {
        __syncthreads();
        const size_t base_k = (size_t)(b * NN + kt * 64) * C3 + CC + (size_t)h * DD;
        const size_t base_v = base_k + CC;
#pragma unroll
        for (int i = 0; i < 8; i++) {
            int idx = tid + i * 128;
            int row = idx >> 4, c4 = (idx & 15) * 4;
            float4 kv = *reinterpret_cast<const float4*>(&g_qkv[base_k + (size_t)row * C3 + c4]);
            uint4 uk;
            uk.x = f2tf32(kv.x); uk.y = f2tf32(kv.y);
            uk.z = f2tf32(kv.z); uk.w = f2tf32(kv.w);
            *reinterpret_cast<uint4*>(&Ks[row * KSTR + c4]) = uk;
            float4 vv = *reinterpret_cast<const float4*>(&g_qkv[base_v + (size_t)row * C3 + c4]);
            uint4 uv;
            uv.x = f2tf32(vv.x); uv.y = f2tf32(vv.y);
            uv.z = f2tf32(vv.z); uv.w = f2tf32(vv.w);
            *reinterpret_cast<uint4*>(&Vs[row * VSTR + c4]) = uv;
        }
        __syncthreads();

        float s[2][8][4];
#pragma unroll
        for (int mi = 0; mi < 2; mi++)
#pragma unroll
            for (int nf = 0; nf < 8; nf++)
#pragma unroll
                for (int j = 0; j < 4; j++) s[mi][nf][j] = 0.f;

#pragma unroll
        for (int kc = 0; kc < 8; kc++) {
            const int k0 = kc * 8;
            uint32_t a[2][4];
#pragma unroll
            for (int mi = 0; mi < 2; mi++) {
                int rr = wq0 + mi * 16;
                a[mi][0] = Qs[(rr + gID) * QSTR + k0 + tig];
                a[mi][1] = Qs[(rr + gID + 8) * QSTR + k0 + tig];
                a[mi][2] = Qs[(rr + gID) * QSTR + k0 + tig + 4];
                a[mi][3] = Qs[(rr + gID + 8) * QSTR + k0 + tig + 4];
            }
#pragma unroll
            for (int nf = 0; nf < 8; nf++) {
                uint32_t b0 = Ks[(nf * 8 + gID) * KSTR + k0 + tig];
                uint32_t b1 = Ks[(nf * 8 + gID) * KSTR + k0 + tig + 4];
                MMA_TF32(s[0][nf], a[0][0], a[0][1], a[0][2], a[0][3], b0, b1);
                MMA_TF32(s[1][nf], a[1][0], a[1][1], a[1][2], a[1][3], b0, b1);
            }
        }

#pragma unroll
        for (int mi = 0; mi < 2; mi++) {
            float mx0 = -1e30f, mx1 = -1e30f;
#pragma unroll
            for (int nf = 0; nf < 8; nf++) {
                mx0 = fmaxf(mx0, fmaxf(s[mi][nf][0], s[mi][nf][1]));
                mx1 = fmaxf(mx1, fmaxf(s[mi][nf][2], s[mi][nf][3]));
            }
            mx0 = fmaxf(mx0, __shfl_xor_sync(0xffffffffu, mx0, 1));
            mx0 = fmaxf(mx0, __shfl_xor_sync(0xffffffffu, mx0, 2));
            mx1 = fmaxf(mx1, __shfl_xor_sync(0xffffffffu, mx1, 1));
            mx1 = fmaxf(mx1, __shfl_xor_sync(0xffffffffu, mx1, 2));

            float mn0 = fmaxf(m[mi][0], mx0), mn1 = fmaxf(m[mi][1], mx1);
            float corr0 = __expf(m[mi][0] - mn0), corr1 = __expf(m[mi][1] - mn1);
            float rs0 = 0.f, rs1 = 0.f;
            int rr = wq0 + mi * 16;
#pragma unroll
            for (int nf = 0; nf < 8; nf++) {
                s[mi][nf][0] = __expf(s[mi][nf][0] - mn0);
                s[mi][nf][1] = __expf(s[mi][nf][1] - mn0);
                s[mi][nf][2] = __expf(s[mi][nf][2] - mn1);
                s[mi][nf][3] = __expf(s[mi][nf][3] - mn1);
                rs0 += s[mi][nf][0] + s[mi][nf][1];
                rs1 += s[mi][nf][2] + s[mi][nf][3];
                uint2 p0 = make_uint2(f2tf32(s[mi][nf][0]), f2tf32(s[mi][nf][1]));
                uint2 p1 = make_uint2(f2tf32(s[mi][nf][2]), f2tf32(s[mi][nf][3]));
                *reinterpret_cast<uint2*>(&Ps[(rr + gID) * PSTR + nf * 8 + 2 * tig]) = p0;
                *reinterpret_cast<uint2*>(&Ps[(rr + gID + 8) * PSTR + nf * 8 + 2 * tig]) = p1;
            }
            rs0 += __shfl_xor_sync(0xffffffffu, rs0, 1);
            rs0 += __shfl_xor_sync(0xffffffffu, rs0, 2);
            rs1 += __shfl_xor_sync(0xffffffffu, rs1, 1);
            rs1 += __shfl_xor_sync(0xffffffffu, rs1, 2);
            l[mi][0] = l[mi][0] * corr0 + rs0;
            l[mi][1] = l[mi][1] * corr1 + rs1;
            m[mi][0] = mn0; m[mi][1] = mn1;
#pragma unroll
            for (int nf = 0; nf < 8; nf++) {
                o[mi][nf][0] *= corr0; o[mi][nf][1] *= corr0;
                o[mi][nf][2] *= corr1; o[mi][nf][3] *= corr1;
            }
        }
        __syncwarp();

#pragma unroll
        for (int kc = 0; kc < 8; kc++) {
            const int k0 = kc * 8;
            uint32_t a[2][4];
#pragma unroll
            for (int mi = 0; mi < 2; mi++) {
                int rr = wq0 + mi * 16;
                a[mi][0] = Ps[(rr + gID) * PSTR + k0 + tig];
                a[mi][1] = Ps[(rr + gID + 8) * PSTR + k0 + tig];
                a[mi][2] = Ps[(rr + gID) * PSTR + k0 + tig + 4];
                a[mi][3] = Ps[(rr + gID + 8) * PSTR + k0 + tig + 4];
            }
#pragma unroll
            for (int nf = 0; nf < 8; nf++) {
                uint32_t b0 = Vs[(k0 + tig) * VSTR + nf * 8 + gID];
                uint32_t b1 = Vs[(k0 + tig + 4) * VSTR + nf * 8 + gID];
                MMA_TF32(o[0][nf], a[0][0], a[0][1], a[0][2], a[0][3], b0, b1);
                MMA_TF32(o[1][nf], a[1][0], a[1][1], a[1][2], a[1][3], b0, b1);
            }
        }
    }

#pragma unroll
    for (int mi = 0; mi < 2; mi++) {
        float inv0 = 1.0f / l[mi][0], inv1 = 1.0f / l[mi][1];
        int row0 = qt * 128 + wq0 + mi * 16 + gID;
#pragma unroll
        for (int nf = 0; nf < 8; nf++) {
            int col = h * DD + nf * 8 + 2 * tig;
            float2 v0 = make_float2(o[mi][nf][0] * inv0, o[mi][nf][1] * inv0);
            float2 v1 = make_float2(o[mi][nf][2] * inv1, o[mi][nf][3] * inv1);
            *reinterpret_cast<float2*>(&g_o[(size_t)(b * NN + row0) * CC + col]) = v0;
            *reinterpret_cast<float2*>(&g_o[(size_t)(b * NN + row0 + 8) * CC + col]) = v1;
        }
    }
}

// ----------------------------------------------------------------------------
extern "C" void kernel_launch(void* const* d_in, const int* in_sizes, int n_in,
                              void* d_out, int out_size) {
    const float* x      = (const float*)d_in[0];
    const float* w_qkv  = (const float*)d_in[1];
    const float* b_qkv  = (const float*)d_in[2];
    const float* gq     = (const float*)d_in[3];
    const float* gk     = (const float*)d_in[4];
    const float* w_proj = (const float*)d_in[5];
    const float* b_proj = (const float*)d_in[6];
    float* out = (float*)d_out;

    float *qkv_ptr = nullptr, *o_ptr = nullptr;
    __half *xh = nullptr, *oh = nullptr, *wqkvTh = nullptr, *wprojTh = nullptr;
    cudaGetSymbolAddress((void**)&qkv_ptr, g_qkv);
    cudaGetSymbolAddress((void**)&o_ptr, g_o);
    cudaGetSymbolAddress((void**)&xh, g_xh);
    cudaGetSymbolAddress((void**)&oh, g_oh);
    cudaGetSymbolAddress((void**)&wqkvTh, g_wqkvTh);
    cudaGetSymbolAddress((void**)&wprojTh, g_wprojTh);

    // 0) weight transpose+convert, x convert
    {
        dim3 blk(32, 8);
        transpose_h_kernel<<<dim3(C3 / 32, CC / 32), blk>>>(w_qkv, wqkvTh, CC, C3);
        transpose_h_kernel<<<dim3(CC / 32, CC / 32), blk>>>(w_proj, wprojTh, CC, CC);
        hconv_kernel<<<(MM * CC / 8) / 256, 256>>>(x, xh);
    }

    // 1) QKV GEMM (fp16 in, f32 out)
    {
        dim3 grid(C3 / 128, MM / 128);
        gemm_h_kernel<<<grid, 256>>>(xh, wqkvTh, b_qkv, qkv_ptr, MM, C3, CC);
    }

    // 2) head layernorm q,k in place (f32)
    {
        int total_warps = 2 * MM * HH;
        qk_norm_kernel<<<total_warps / 8, 256>>>(gq, gk);
    }

    // 3) flash attention (tf32 mma, R5 exact)
    {
        cudaFuncSetAttribute(flash_mma_kernel, cudaFuncAttributeMaxDynamicSharedMemorySize, FLASH_SMEM);
        dim3 grid(NN / 128, BB * HH);
        flash_mma_kernel<<<grid, 128, FLASH_SMEM>>>();
    }

    // 4) attn out -> fp16, then projection (fp16 in, f32 out)
    {
        hconv_kernel<<<(MM * CC / 8) / 256, 256>>>(o_ptr, oh);
        dim3 grid(CC / 128, MM / 128);
        gemm_h_kernel<<<grid, 256>>>(oh, wprojTh, b_proj, out, MM, CC, CC);
    }
}

// round 9
// speedup vs baseline: 5.2225x; 1.1671x over previous
#include <cuda_runtime.h>
#include <cuda_fp16.h>
#include <cstdint>
#include <math.h>

// Problem constants
#define BB 4
#define NN 2048
#define CC 1024
#define HH 16
#define DD 64
#define MM (BB * NN)          // 8192
#define C3 (3 * CC)           // 3072
#define EPSV 1e-6f

// Scratch (16B-aligned)
__device__ __align__(16) float  g_qkv[(size_t)MM * C3];       // 96 MB
__device__ __align__(16) __half g_xh[(size_t)MM * CC];        // 16 MB
__device__ __align__(16) __half g_oh[(size_t)MM * CC];        // 16 MB (flash writes fp16)
__device__ __align__(16) __half g_wqkvTh[(size_t)C3 * CC];    // 6 MB
__device__ __align__(16) __half g_wprojTh[(size_t)CC * CC];   // 2 MB

__device__ __forceinline__ uint32_t f2h2(float lo, float hi) {
    __half2 h = __float22half2_rn(make_float2(lo, hi));
    return *reinterpret_cast<uint32_t*>(&h);
}

#define MMA_F16(c, a0, a1, a2, a3, b0, b1)                                     \
    asm volatile(                                                               \
        "mma.sync.aligned.m16n8k16.row.col.f32.f16.f16.f32 "                    \
        "{%0,%1,%2,%3}, {%4,%5,%6,%7}, {%8,%9}, {%0,%1,%2,%3};"                 \
        : "+f"((c)[0]), "+f"((c)[1]), "+f"((c)[2]), "+f"((c)[3])                \
        : "r"(a0), "r"(a1), "r"(a2), "r"(a3), "r"(b0), "r"(b1))

// ---------------------------------------------------------------------------
// Weight transpose + fp16 convert: in[R][Cn] f32 -> out[Cn][R] fp16
// ---------------------------------------------------------------------------
__global__ void transpose_h_kernel(const float* __restrict__ in, __half* __restrict__ out,
                                   int R, int Cn) {
    __shared__ float t[32][33];
    int bx = blockIdx.x * 32, by = blockIdx.y * 32;
#pragma unroll
    for (int i = 0; i < 32; i += 8)
        t[threadIdx.y + i][threadIdx.x] = in[(size_t)(by + threadIdx.y + i) * Cn + bx + threadIdx.x];
    __syncthreads();
#pragma unroll
    for (int i = 0; i < 32; i += 8)
        out[(size_t)(bx + threadIdx.y + i) * R + by + threadIdx.x] =
            __float2half(t[threadIdx.x][threadIdx.y + i]);
}

// ---------------------------------------------------------------------------
// f32 -> fp16 bulk convert (8 elems/thread)
// ---------------------------------------------------------------------------
__global__ void hconv_kernel(const float* __restrict__ src, __half* __restrict__ dst) {
    size_t i = (size_t)blockIdx.x * blockDim.x + threadIdx.x;
    const float4* p = reinterpret_cast<const float4*>(src) + 2 * i;
    float4 a = p[0], b = p[1];
    uint4 u;
    u.x = f2h2(a.x, a.y); u.y = f2h2(a.z, a.w);
    u.z = f2h2(b.x, b.y); u.w = f2h2(b.z, b.w);
    reinterpret_cast<uint4*>(dst)[i] = u;
}

// ---------------------------------------------------------------------------
// fp16 mma.sync GEMM (R8 exact): C[M,N] = Ah[M,K] @ BTh[N,K]^T + bias[N]
// ---------------------------------------------------------------------------
#define GSTR 20

__global__ void __launch_bounds__(256)
gemm_h_kernel(const __half* __restrict__ Ah, const __half* __restrict__ BTh,
              const float* __restrict__ bias, float* __restrict__ Cmat,
              int M, int N, int K) {
    __shared__ uint32_t As2[2][128 * GSTR];
    __shared__ uint32_t Bs2[2][128 * GSTR];

    const int tid = threadIdx.x;
    const int wid = tid >> 5;
    const int lane = tid & 31;
    const int gID = lane >> 2;
    const int tig = lane & 3;
    const int wm = (wid & 1) * 64;
    const int wn = (wid >> 1) * 32;
    const int bm = blockIdx.y * 128;
    const int bn = blockIdx.x * 128;

    const int lrow = tid >> 1;
    const int lhalf = (tid & 1) * 8;
    const __half* Agp = Ah + (size_t)(bm + lrow) * K + (tid & 1) * 16;
    const __half* Bgp = BTh + (size_t)(bn + lrow) * K + (tid & 1) * 16;

    float acc[4][4][4];
#pragma unroll
    for (int mi = 0; mi < 4; mi++)
#pragma unroll
        for (int ni = 0; ni < 4; ni++)
#pragma unroll
            for (int r = 0; r < 4; r++) acc[mi][ni][r] = 0.f;

    uint4 rA0 = *reinterpret_cast<const uint4*>(Agp);
    uint4 rA1 = *reinterpret_cast<const uint4*>(Agp + 8);
    uint4 rB0 = *reinterpret_cast<const uint4*>(Bgp);
    uint4 rB1 = *reinterpret_cast<const uint4*>(Bgp + 8);
    *reinterpret_cast<uint4*>(&As2[0][lrow * GSTR + lhalf]) = rA0;
    *reinterpret_cast<uint4*>(&As2[0][lrow * GSTR + lhalf + 4]) = rA1;
    *reinterpret_cast<uint4*>(&Bs2[0][lrow * GSTR + lhalf]) = rB0;
    *reinterpret_cast<uint4*>(&Bs2[0][lrow * GSTR + lhalf + 4]) = rB1;
    __syncthreads();

    const int S = K / 32;
    for (int s = 0; s < S; s++) {
        const int buf = s & 1;
        if (s + 1 < S) {
            Agp += 32; Bgp += 32;
            rA0 = *reinterpret_cast<const uint4*>(Agp);
            rA1 = *reinterpret_cast<const uint4*>(Agp + 8);
            rB0 = *reinterpret_cast<const uint4*>(Bgp);
            rB1 = *reinterpret_cast<const uint4*>(Bgp + 8);
        }

#pragma unroll
        for (int j = 0; j < 2; j++) {
            const int k2 = j * 8;
            uint32_t af[4][4], bf[4][2];
#pragma unroll
            for (int mi = 0; mi < 4; mi++) {
                int r0 = wm + mi * 16 + gID;
                af[mi][0] = As2[buf][r0 * GSTR + k2 + tig];
                af[mi][1] = As2[buf][(r0 + 8) * GSTR + k2 + tig];
                af[mi][2] = As2[buf][r0 * GSTR + k2 + tig + 4];
                af[mi][3] = As2[buf][(r0 + 8) * GSTR + k2 + tig + 4];
            }
#pragma unroll
            for (int ni = 0; ni < 4; ni++) {
                int n0 = wn + ni * 8 + gID;
                bf[ni][0] = Bs2[buf][n0 * GSTR + k2 + tig];
                bf[ni][1] = Bs2[buf][n0 * GSTR + k2 + tig + 4];
            }
#pragma unroll
            for (int mi = 0; mi < 4; mi++)
#pragma unroll
                for (int ni = 0; ni < 4; ni++)
                    MMA_F16(acc[mi][ni], af[mi][0], af[mi][1], af[mi][2], af[mi][3],
                            bf[ni][0], bf[ni][1]);
        }

        if (s + 1 < S) {
            *reinterpret_cast<uint4*>(&As2[buf ^ 1][lrow * GSTR + lhalf]) = rA0;
            *reinterpret_cast<uint4*>(&As2[buf ^ 1][lrow * GSTR + lhalf + 4]) = rA1;
            *reinterpret_cast<uint4*>(&Bs2[buf ^ 1][lrow * GSTR + lhalf]) = rB0;
            *reinterpret_cast<uint4*>(&Bs2[buf ^ 1][lrow * GSTR + lhalf + 4]) = rB1;
            __syncthreads();
        }
    }

#pragma unroll
    for (int mi = 0; mi < 4; mi++) {
        int row0 = bm + wm + mi * 16 + gID;
#pragma unroll
        for (int ni = 0; ni < 4; ni++) {
            int col = bn + wn + ni * 8 + 2 * tig;
            float b0 = bias[col], b1 = bias[col + 1];
            float2 v0 = make_float2(acc[mi][ni][0] + b0, acc[mi][ni][1] + b1);
            float2 v1 = make_float2(acc[mi][ni][2] + b0, acc[mi][ni][3] + b1);
            *reinterpret_cast<float2*>(Cmat + (size_t)row0 * N + col) = v0;
            *reinterpret_cast<float2*>(Cmat + (size_t)(row0 + 8) * N + col) = v1;
        }
    }
}

// ----------------------------------------------------------------------------
// Head LayerNorm on q and k, in place in g_qkv (R5 exact).
// ----------------------------------------------------------------------------
__global__ void qk_norm_kernel(const float* __restrict__ gamma_q,
                               const float* __restrict__ gamma_k) {
    int gwarp = (blockIdx.x * blockDim.x + threadIdx.x) >> 5;
    int lane = threadIdx.x & 31;
    int comp = gwarp & 1;
    int r = gwarp >> 1;
    int h = r & (HH - 1);
    int bn = r >> 4;

    float* ptr = g_qkv + (size_t)bn * C3 + comp * CC + h * DD;
    float2 v = *reinterpret_cast<float2*>(ptr + lane * 2);

    float s = v.x + v.y;
#pragma unroll
    for (int off = 16; off >= 1; off >>= 1) s += __shfl_xor_sync(0xffffffffu, s, off);
    float mu = s * (1.0f / 64.0f);

    float dx = v.x - mu, dy = v.y - mu;
    float e = dx * dx + dy * dy;
#pragma unroll
    for (int off = 16; off >= 1; off >>= 1) e += __shfl_xor_sync(0xffffffffu, e, off);
    float rs = rsqrtf(e * (1.0f / 64.0f) + EPSV);

    const float* gamma = comp ? gamma_k : gamma_q;
    float2 o;
    o.x = dx * rs * gamma[lane * 2 + 0];
    o.y = dy * rs * gamma[lane * 2 + 1];
    *reinterpret_cast<float2*>(ptr + lane * 2) = o;
}

// ----------------------------------------------------------------------------
// Flash attention fp16 m16n8k16. CTA = 128 q rows, 4 warps, KV tile 64.
// Smem u32-packed fp16 pairs, stride 36 u32 (conflict-free frag loads).
// Q scaled 0.125 at load. V transposed to Vt[d][kv-pair] via f2h2 of 2 rows.
// Output written fp16 directly to g_oh [b*n][h*d].
// ----------------------------------------------------------------------------
#define FSTR 36
#define FLASH_SMEM ((128 * FSTR + 64 * FSTR + 64 * FSTR + 128 * FSTR) * 4)

__global__ void __launch_bounds__(128) flash_h_kernel() {
    extern __shared__ uint32_t sm[];
    uint32_t* Qs = sm;                    // 128 rows x 32 u32 (d-pairs)
    uint32_t* Ks = Qs + 128 * FSTR;       // 64 rows x 32 u32 (d-pairs)
    uint32_t* Vt = Ks + 64 * FSTR;        // 64 d-rows x 32 u32 (kv-pairs)
    uint32_t* Ps = Vt + 64 * FSTR;        // 128 rows x 32 u32 (kv-pairs)

    const int tid = threadIdx.x;
    const int wid = tid >> 5;
    const int lane = tid & 31;
    const int gID = lane >> 2;
    const int tig = lane & 3;
    const int qt = blockIdx.x;            // 0..15
    const int bh = blockIdx.y;            // 0..63
    const int b = bh >> 4;
    const int h = bh & 15;
    const int wq0 = wid * 32;

    // Q tile: 128 rows x 64 f32 -> fp16 pairs, scaled 0.125
    const size_t base_q = (size_t)(b * NN + qt * 128) * C3 + (size_t)h * DD;
#pragma unroll
    for (int i = 0; i < 16; i++) {
        int idx = tid + i * 128;
        int row = idx >> 4, c4 = (idx & 15) * 4;          // float offset in row
        float4 v = *reinterpret_cast<const float4*>(&g_qkv[base_q + (size_t)row * C3 + c4]);
        uint2 u = make_uint2(f2h2(v.x * 0.125f, v.y * 0.125f),
                             f2h2(v.z * 0.125f, v.w * 0.125f));
        *reinterpret_cast<uint2*>(&Qs[row * FSTR + (idx & 15) * 2]) = u;
    }

    float m[2][2], l[2][2], o[2][8][4];
#pragma unroll
    for (int mi = 0; mi < 2; mi++) {
        m[mi][0] = -1e30f; m[mi][1] = -1e30f;
        l[mi][0] = 0.f; l[mi][1] = 0.f;
#pragma unroll
        for (int nf = 0; nf < 8; nf++)
#pragma unroll
            for (int j = 0; j < 4; j++) o[mi][nf][j] = 0.f;
    }

    const int kv2 = tid & 31;             // 0..31: kv pair index
    const int dg = tid >> 5;              // 0..3:  16-d chunk

    for (int kt = 0; kt < NN / 64; kt++) {
        __syncthreads();   // prior-iter K/V/P reads complete (covers Q stores on kt=0)
        const size_t base_k = (size_t)(b * NN + kt * 64) * C3 + CC + (size_t)h * DD;
        const size_t base_v = base_k + CC;

        // K tile: 64 rows x 64 f32 -> fp16 pairs
#pragma unroll
        for (int i = 0; i < 8; i++) {
            int idx = tid + i * 128;
            int row = idx >> 4, c4 = (idx & 15) * 4;
            float4 kv = *reinterpret_cast<const float4*>(&g_qkv[base_k + (size_t)row * C3 + c4]);
            uint2 u = make_uint2(f2h2(kv.x, kv.y), f2h2(kv.z, kv.w));
            *reinterpret_cast<uint2*>(&Ks[row * FSTR + (idx & 15) * 2]) = u;
        }

        // V tile transpose: thread owns kv rows {2*kv2, 2*kv2+1}, d chunk dg*16..+15
        {
            const float* r0p = &g_qkv[base_v + (size_t)(2 * kv2) * C3 + dg * 16];
            const float* r1p = r0p + C3;
            float4 a0 = *reinterpret_cast<const float4*>(r0p + 0);
            float4 a1 = *reinterpret_cast<const float4*>(r0p + 4);
            float4 a2 = *reinterpret_cast<const float4*>(r0p + 8);
            float4 a3 = *reinterpret_cast<const float4*>(r0p + 12);
            float4 c0 = *reinterpret_cast<const float4*>(r1p + 0);
            float4 c1 = *reinterpret_cast<const float4*>(r1p + 4);
            float4 c2 = *reinterpret_cast<const float4*>(r1p + 8);
            float4 c3 = *reinterpret_cast<const float4*>(r1p + 12);
            uint32_t* vt = &Vt[(dg * 16) * FSTR + kv2];
            vt[0 * FSTR]  = f2h2(a0.x, c0.x);
            vt[1 * FSTR]  = f2h2(a0.y, c0.y);
            vt[2 * FSTR]  = f2h2(a0.z, c0.z);
            vt[3 * FSTR]  = f2h2(a0.w, c0.w);
            vt[4 * FSTR]  = f2h2(a1.x, c1.x);
            vt[5 * FSTR]  = f2h2(a1.y, c1.y);
            vt[6 * FSTR]  = f2h2(a1.z, c1.z);
            vt[7 * FSTR]  = f2h2(a1.w, c1.w);
            vt[8 * FSTR]  = f2h2(a2.x, c2.x);
            vt[9 * FSTR]  = f2h2(a2.y, c2.y);
            vt[10 * FSTR] = f2h2(a2.z, c2.z);
            vt[11 * FSTR] = f2h2(a2.w, c2.w);
            vt[12 * FSTR] = f2h2(a3.x, c3.x);
            vt[13 * FSTR] = f2h2(a3.y, c3.y);
            vt[14 * FSTR] = f2h2(a3.z, c3.z);
            vt[15 * FSTR] = f2h2(a3.w, c3.w);
        }
        __syncthreads();

        // S = Q @ K^T  (2 m-frags x 8 n-frags, 4 k16 steps)
        float s[2][8][4];
#pragma unroll
        for (int mi = 0; mi < 2; mi++)
#pragma unroll
            for (int nf = 0; nf < 8; nf++)
#pragma unroll
                for (int j = 0; j < 4; j++) s[mi][nf][j] = 0.f;

#pragma unroll
        for (int j = 0; j < 4; j++) {
            const int k0 = j * 8;
            uint32_t a[2][4];
#pragma unroll
            for (int mi = 0; mi < 2; mi++) {
                int rr = wq0 + mi * 16;
                a[mi][0] = Qs[(rr + gID) * FSTR + k0 + tig];
                a[mi][1] = Qs[(rr + gID + 8) * FSTR + k0 + tig];
                a[mi][2] = Qs[(rr + gID) * FSTR + k0 + tig + 4];
                a[mi][3] = Qs[(rr + gID + 8) * FSTR + k0 + tig + 4];
            }
#pragma unroll
            for (int nf = 0; nf < 8; nf++) {
                uint32_t b0 = Ks[(nf * 8 + gID) * FSTR + k0 + tig];
                uint32_t b1 = Ks[(nf * 8 + gID) * FSTR + k0 + tig + 4];
                MMA_F16(s[0][nf], a[0][0], a[0][1], a[0][2], a[0][3], b0, b1);
                MMA_F16(s[1][nf], a[1][0], a[1][1], a[1][2], a[1][3], b0, b1);
            }
        }

        // online softmax per m-frag (rows gID: c0,c1; gID+8: c2,c3)
#pragma unroll
        for (int mi = 0; mi < 2; mi++) {
            float mx0 = -1e30f, mx1 = -1e30f;
#pragma unroll
            for (int nf = 0; nf < 8; nf++) {
                mx0 = fmaxf(mx0, fmaxf(s[mi][nf][0], s[mi][nf][1]));
                mx1 = fmaxf(mx1, fmaxf(s[mi][nf][2], s[mi][nf][3]));
            }
            mx0 = fmaxf(mx0, __shfl_xor_sync(0xffffffffu, mx0, 1));
            mx0 = fmaxf(mx0, __shfl_xor_sync(0xffffffffu, mx0, 2));
            mx1 = fmaxf(mx1, __shfl_xor_sync(0xffffffffu, mx1, 1));
            mx1 = fmaxf(mx1, __shfl_xor_sync(0xffffffffu, mx1, 2));

            float mn0 = fmaxf(m[mi][0], mx0), mn1 = fmaxf(m[mi][1], mx1);
            float corr0 = __expf(m[mi][0] - mn0), corr1 = __expf(m[mi][1] - mn1);
            float rs0 = 0.f, rs1 = 0.f;
            int rr = wq0 + mi * 16;
#pragma unroll
            for (int nf = 0; nf < 8; nf++) {
                s[mi][nf][0] = __expf(s[mi][nf][0] - mn0);
                s[mi][nf][1] = __expf(s[mi][nf][1] - mn0);
                s[mi][nf][2] = __expf(s[mi][nf][2] - mn1);
                s[mi][nf][3] = __expf(s[mi][nf][3] - mn1);
                rs0 += s[mi][nf][0] + s[mi][nf][1];
                rs1 += s[mi][nf][2] + s[mi][nf][3];
                // P pair (kv = nf*8+2tig, +1) -> u32 index nf*4+tig
                Ps[(rr + gID) * FSTR + nf * 4 + tig]     = f2h2(s[mi][nf][0], s[mi][nf][1]);
                Ps[(rr + gID + 8) * FSTR + nf * 4 + tig] = f2h2(s[mi][nf][2], s[mi][nf][3]);
            }
            rs0 += __shfl_xor_sync(0xffffffffu, rs0, 1);
            rs0 += __shfl_xor_sync(0xffffffffu, rs0, 2);
            rs1 += __shfl_xor_sync(0xffffffffu, rs1, 1);
            rs1 += __shfl_xor_sync(0xffffffffu, rs1, 2);
            l[mi][0] = l[mi][0] * corr0 + rs0;
            l[mi][1] = l[mi][1] * corr1 + rs1;
            m[mi][0] = mn0; m[mi][1] = mn1;
#pragma unroll
            for (int nf = 0; nf < 8; nf++) {
                o[mi][nf][0] *= corr0; o[mi][nf][1] *= corr0;
                o[mi][nf][2] *= corr1; o[mi][nf][3] *= corr1;
            }
        }
        __syncwarp();   // Ps rows are warp-private

        // O += P @ V   (4 k16 steps over kv; B from Vt[d][kv-pairs])
#pragma unroll
        for (int j = 0; j < 4; j++) {
            const int k0 = j * 8;
            uint32_t a[2][4];
#pragma unroll
            for (int mi = 0; mi < 2; mi++) {
                int rr = wq0 + mi * 16;
                a[mi][0] = Ps[(rr + gID) * FSTR + k0 + tig];
                a[mi][1] = Ps[(rr + gID + 8) * FSTR + k0 + tig];
                a[mi][2] = Ps[(rr + gID) * FSTR + k0 + tig + 4];
                a[mi][3] = Ps[(rr + gID + 8) * FSTR + k0 + tig + 4];
            }
#pragma unroll
            for (int nf = 0; nf < 8; nf++) {
                uint32_t b0 = Vt[(nf * 8 + gID) * FSTR + k0 + tig];
                uint32_t b1 = Vt[(nf * 8 + gID) * FSTR + k0 + tig + 4];
                MMA_F16(o[0][nf], a[0][0], a[0][1], a[0][2], a[0][3], b0, b1);
                MMA_F16(o[1][nf], a[1][0], a[1][1], a[1][2], a[1][3], b0, b1);
            }
        }
    }

    // normalize + store fp16 to g_oh [b*n][h*d]
#pragma unroll
    for (int mi = 0; mi < 2; mi++) {
        float inv0 = 1.0f / l[mi][0], inv1 = 1.0f / l[mi][1];
        int row0 = qt * 128 + wq0 + mi * 16 + gID;
#pragma unroll
        for (int nf = 0; nf < 8; nf++) {
            int col = h * DD + nf * 8 + 2 * tig;
            *reinterpret_cast<uint32_t*>(g_oh + (size_t)(b * NN + row0) * CC + col) =
                f2h2(o[mi][nf][0] * inv0, o[mi][nf][1] * inv0);
            *reinterpret_cast<uint32_t*>(g_oh + (size_t)(b * NN + row0 + 8) * CC + col) =
                f2h2(o[mi][nf][2] * inv1, o[mi][nf][3] * inv1);
        }
    }
}

// ----------------------------------------------------------------------------
extern "C" void kernel_launch(void* const* d_in, const int* in_sizes, int n_in,
                              void* d_out, int out_size) {
    const float* x      = (const float*)d_in[0];
    const float* w_qkv  = (const float*)d_in[1];
    const float* b_qkv  = (const float*)d_in[2];
    const float* gq     = (const float*)d_in[3];
    const float* gk     = (const float*)d_in[4];
    const float* w_proj = (const float*)d_in[5];
    const float* b_proj = (const float*)d_in[6];
    float* out = (float*)d_out;

    float* qkv_ptr = nullptr;
    __half *xh = nullptr, *oh = nullptr, *wqkvTh = nullptr, *wprojTh = nullptr;
    cudaGetSymbolAddress((void**)&qkv_ptr, g_qkv);
    cudaGetSymbolAddress((void**)&xh, g_xh);
    cudaGetSymbolAddress((void**)&oh, g_oh);
    cudaGetSymbolAddress((void**)&wqkvTh, g_wqkvTh);
    cudaGetSymbolAddress((void**)&wprojTh, g_wprojTh);

    // 0) weight transpose+convert, x convert
    {
        dim3 blk(32, 8);
        transpose_h_kernel<<<dim3(C3 / 32, CC / 32), blk>>>(w_qkv, wqkvTh, CC, C3);
        transpose_h_kernel<<<dim3(CC / 32, CC / 32), blk>>>(w_proj, wprojTh, CC, CC);
        hconv_kernel<<<(MM * CC / 8) / 256, 256>>>(x, xh);
    }

    // 1) QKV GEMM (fp16 in, f32 out)
    {
        dim3 grid(C3 / 128, MM / 128);
        gemm_h_kernel<<<grid, 256>>>(xh, wqkvTh, b_qkv, qkv_ptr, MM, C3, CC);
    }

    // 2) head layernorm q,k in place (f32)
    {
        int total_warps = 2 * MM * HH;
        qk_norm_kernel<<<total_warps / 8, 256>>>(gq, gk);
    }

    // 3) flash attention (fp16 mma), writes fp16 g_oh
    {
        cudaFuncSetAttribute(flash_h_kernel, cudaFuncAttributeMaxDynamicSharedMemorySize, FLASH_SMEM);
        dim3 grid(NN / 128, BB * HH);
        flash_h_kernel<<<grid, 128, FLASH_SMEM>>>();
    }

    // 4) output projection (fp16 in, f32 out)
    {
        dim3 grid(CC / 128, MM / 128);
        gemm_h_kernel<<<grid, 256>>>(oh, wprojTh, b_proj, out, MM, CC, CC);
    }
}

// round 10
// speedup vs baseline: 5.6078x; 1.0738x over previous
#include <cuda_runtime.h>
#include <cuda_fp16.h>
#include <cstdint>
#include <math.h>

// Problem constants
#define BB 4
#define NN 2048
#define CC 1024
#define HH 16
#define DD 64
#define MM (BB * NN)          // 8192
#define C3 (3 * CC)           // 3072
#define EPSV 1e-6f

// Scratch (16B-aligned)
__device__ __align__(16) float  g_qkv[(size_t)MM * C3];       // 96 MB
__device__ __align__(16) __half g_xh[(size_t)MM * CC];        // 16 MB
__device__ __align__(16) __half g_oh[(size_t)MM * CC];        // 16 MB
__device__ __align__(16) __half g_wqkvTh[(size_t)C3 * CC];    // 6 MB
__device__ __align__(16) __half g_wprojTh[(size_t)CC * CC];   // 2 MB

__device__ __forceinline__ uint32_t f2h2(float lo, float hi) {
    __half2 h = __float22half2_rn(make_float2(lo, hi));
    return *reinterpret_cast<uint32_t*>(&h);
}
__device__ __forceinline__ uint32_t smem_u32(const void* p) {
    uint32_t a;
    asm("{ .reg .u64 t; cvta.to.shared.u64 t, %1; cvt.u32.u64 %0, t; }" : "=r"(a) : "l"(p));
    return a;
}

#define MMA_F16(c, a0, a1, a2, a3, b0, b1)                                     \
    asm volatile(                                                               \
        "mma.sync.aligned.m16n8k16.row.col.f32.f16.f16.f32 "                    \
        "{%0,%1,%2,%3}, {%4,%5,%6,%7}, {%8,%9}, {%0,%1,%2,%3};"                 \
        : "+f"((c)[0]), "+f"((c)[1]), "+f"((c)[2]), "+f"((c)[3])                \
        : "r"(a0), "r"(a1), "r"(a2), "r"(a3), "r"(b0), "r"(b1))

#define LDM_X4(r0, r1, r2, r3, addr)                                           \
    asm volatile("ldmatrix.sync.aligned.m8n8.x4.shared.b16 {%0,%1,%2,%3}, [%4];" \
        : "=r"(r0), "=r"(r1), "=r"(r2), "=r"(r3) : "r"(addr))

// ---------------------------------------------------------------------------
// Weight transpose + fp16 convert: in[R][Cn] f32 -> out[Cn][R] fp16
// ---------------------------------------------------------------------------
__global__ void transpose_h_kernel(const float* __restrict__ in, __half* __restrict__ out,
                                   int R, int Cn) {
    __shared__ float t[32][33];
    int bx = blockIdx.x * 32, by = blockIdx.y * 32;
#pragma unroll
    for (int i = 0; i < 32; i += 8)
        t[threadIdx.y + i][threadIdx.x] = in[(size_t)(by + threadIdx.y + i) * Cn + bx + threadIdx.x];
    __syncthreads();
#pragma unroll
    for (int i = 0; i < 32; i += 8)
        out[(size_t)(bx + threadIdx.y + i) * R + by + threadIdx.x] =
            __float2half(t[threadIdx.x][threadIdx.y + i]);
}

// ---------------------------------------------------------------------------
// f32 -> fp16 bulk convert (8 elems/thread)
// ---------------------------------------------------------------------------
__global__ void hconv_kernel(const float* __restrict__ src, __half* __restrict__ dst) {
    size_t i = (size_t)blockIdx.x * blockDim.x + threadIdx.x;
    const float4* p = reinterpret_cast<const float4*>(src) + 2 * i;
    float4 a = p[0], b = p[1];
    uint4 u;
    u.x = f2h2(a.x, a.y); u.y = f2h2(a.z, a.w);
    u.z = f2h2(b.x, b.y); u.w = f2h2(b.z, b.w);
    reinterpret_cast<uint4*>(dst)[i] = u;
}

// ---------------------------------------------------------------------------
// fp16 mma.sync GEMM with ldmatrix fragment loads.
// C[M,N] = Ah[M,K] @ BTh[N,K]^T + bias[N]
// CTA 128x128, BK=32, 8 warps (2m x 4n), warp tile 64x32, double-buffered.
// ---------------------------------------------------------------------------
#define GSTR 20
#define GEMM_BUF_BYTES (128 * GSTR * 4)

__global__ void __launch_bounds__(256)
gemm_h_kernel(const __half* __restrict__ Ah, const __half* __restrict__ BTh,
              const float* __restrict__ bias, float* __restrict__ Cmat,
              int M, int N, int K) {
    __shared__ uint32_t As2[2][128 * GSTR];
    __shared__ uint32_t Bs2[2][128 * GSTR];

    const int tid = threadIdx.x;
    const int wid = tid >> 5;
    const int lane = tid & 31;
    const int gID = lane >> 2;
    const int tig = lane & 3;
    const int grp = lane >> 3;           // 0..3 (ldmatrix address group)
    const int l8 = lane & 7;
    const int wm = (wid & 1) * 64;
    const int wn = (wid >> 1) * 32;
    const int bm = blockIdx.y * 128;
    const int bn = blockIdx.x * 128;

    const int lrow = tid >> 1;
    const int lhalf = (tid & 1) * 8;
    const __half* Agp = Ah + (size_t)(bm + lrow) * K + (tid & 1) * 16;
    const __half* Bgp = BTh + (size_t)(bn + lrow) * K + (tid & 1) * 16;

    // ldmatrix base addresses (bytes) for buf 0, j 0.
    // A x4 (per mi): mats = [m0-7,k0-7],[m8-15,k0-7],[m0-7,k8-15],[m8-15,k8-15]
    //   lane group g: row = wm+mi*16 + (g&1)*8 + l8, u32 col = (g>>1)*4
    // B x4 (per ni2): mats = [n0-7,k0-7],[n0-7,k8-15],[n8-15,k0-7],[n8-15,k8-15]
    //   -> regs bf[2ni2][0], bf[2ni2][1], bf[2ni2+1][0], bf[2ni2+1][1]
    //   lane group g: row = wn+ni2*16 + (g>>1)*8 + l8, u32 col = (g&1)*4
    const uint32_t asBase = smem_u32(As2);
    const uint32_t bsBase = smem_u32(Bs2);
    uint32_t aAddr[4], bAddr[2];
#pragma unroll
    for (int mi = 0; mi < 4; mi++)
        aAddr[mi] = asBase + (((wm + mi * 16 + (grp & 1) * 8 + l8) * GSTR) + (grp >> 1) * 4) * 4;
#pragma unroll
    for (int ni2 = 0; ni2 < 2; ni2++)
        bAddr[ni2] = bsBase + (((wn + ni2 * 16 + (grp >> 1) * 8 + l8) * GSTR) + (grp & 1) * 4) * 4;

    float acc[4][4][4];
#pragma unroll
    for (int mi = 0; mi < 4; mi++)
#pragma unroll
        for (int ni = 0; ni < 4; ni++)
#pragma unroll
            for (int r = 0; r < 4; r++) acc[mi][ni][r] = 0.f;

    uint4 rA0 = *reinterpret_cast<const uint4*>(Agp);
    uint4 rA1 = *reinterpret_cast<const uint4*>(Agp + 8);
    uint4 rB0 = *reinterpret_cast<const uint4*>(Bgp);
    uint4 rB1 = *reinterpret_cast<const uint4*>(Bgp + 8);
    *reinterpret_cast<uint4*>(&As2[0][lrow * GSTR + lhalf]) = rA0;
    *reinterpret_cast<uint4*>(&As2[0][lrow * GSTR + lhalf + 4]) = rA1;
    *reinterpret_cast<uint4*>(&Bs2[0][lrow * GSTR + lhalf]) = rB0;
    *reinterpret_cast<uint4*>(&Bs2[0][lrow * GSTR + lhalf + 4]) = rB1;
    __syncthreads();

    const int S = K / 32;
    for (int s = 0; s < S; s++) {
        const int buf = s & 1;
        const uint32_t bufOff = (uint32_t)buf * GEMM_BUF_BYTES;
        if (s + 1 < S) {
            Agp += 32; Bgp += 32;
            rA0 = *reinterpret_cast<const uint4*>(Agp);
            rA1 = *reinterpret_cast<const uint4*>(Agp + 8);
            rB0 = *reinterpret_cast<const uint4*>(Bgp);
            rB1 = *reinterpret_cast<const uint4*>(Bgp + 8);
        }

#pragma unroll
        for (int j = 0; j < 2; j++) {
            const uint32_t jOff = bufOff + j * 32;   // j*8 u32 = 32 bytes
            uint32_t af[4][4], bf[4][2];
#pragma unroll
            for (int mi = 0; mi < 4; mi++)
                LDM_X4(af[mi][0], af[mi][1], af[mi][2], af[mi][3], aAddr[mi] + jOff);
            LDM_X4(bf[0][0], bf[0][1], bf[1][0], bf[1][1], bAddr[0] + jOff);
            LDM_X4(bf[2][0], bf[2][1], bf[3][0], bf[3][1], bAddr[1] + jOff);
#pragma unroll
            for (int mi = 0; mi < 4; mi++)
#pragma unroll
                for (int ni = 0; ni < 4; ni++)
                    MMA_F16(acc[mi][ni], af[mi][0], af[mi][1], af[mi][2], af[mi][3],
                            bf[ni][0], bf[ni][1]);
        }

        if (s + 1 < S) {
            *reinterpret_cast<uint4*>(&As2[buf ^ 1][lrow * GSTR + lhalf]) = rA0;
            *reinterpret_cast<uint4*>(&As2[buf ^ 1][lrow * GSTR + lhalf + 4]) = rA1;
            *reinterpret_cast<uint4*>(&Bs2[buf ^ 1][lrow * GSTR + lhalf]) = rB0;
            *reinterpret_cast<uint4*>(&Bs2[buf ^ 1][lrow * GSTR + lhalf + 4]) = rB1;
            __syncthreads();
        }
    }

#pragma unroll
    for (int mi = 0; mi < 4; mi++) {
        int row0 = bm + wm + mi * 16 + gID;
#pragma unroll
        for (int ni = 0; ni < 4; ni++) {
            int col = bn + wn + ni * 8 + 2 * tig;
            float b0 = bias[col], b1 = bias[col + 1];
            float2 v0 = make_float2(acc[mi][ni][0] + b0, acc[mi][ni][1] + b1);
            float2 v1 = make_float2(acc[mi][ni][2] + b0, acc[mi][ni][3] + b1);
            *reinterpret_cast<float2*>(Cmat + (size_t)row0 * N + col) = v0;
            *reinterpret_cast<float2*>(Cmat + (size_t)(row0 + 8) * N + col) = v1;
        }
    }
}

// ----------------------------------------------------------------------------
// Head LayerNorm on q and k, in place in g_qkv (R5 exact).
// ----------------------------------------------------------------------------
__global__ void qk_norm_kernel(const float* __restrict__ gamma_q,
                               const float* __restrict__ gamma_k) {
    int gwarp = (blockIdx.x * blockDim.x + threadIdx.x) >> 5;
    int lane = threadIdx.x & 31;
    int comp = gwarp & 1;
    int r = gwarp >> 1;
    int h = r & (HH - 1);
    int bn = r >> 4;

    float* ptr = g_qkv + (size_t)bn * C3 + comp * CC + h * DD;
    float2 v = *reinterpret_cast<float2*>(ptr + lane * 2);

    float s = v.x + v.y;
#pragma unroll
    for (int off = 16; off >= 1; off >>= 1) s += __shfl_xor_sync(0xffffffffu, s, off);
    float mu = s * (1.0f / 64.0f);

    float dx = v.x - mu, dy = v.y - mu;
    float e = dx * dx + dy * dy;
#pragma unroll
    for (int off = 16; off >= 1; off >>= 1) e += __shfl_xor_sync(0xffffffffu, e, off);
    float rs = rsqrtf(e * (1.0f / 64.0f) + EPSV);

    const float* gamma = comp ? gamma_k : gamma_q;
    float2 o;
    o.x = dx * rs * gamma[lane * 2 + 0];
    o.y = dy * rs * gamma[lane * 2 + 1];
    *reinterpret_cast<float2*>(ptr + lane * 2) = o;
}

// ----------------------------------------------------------------------------
// Flash attention fp16 m16n8k16 (R9 exact). CTA = 128 q rows, 4 warps.
// ----------------------------------------------------------------------------
#define FSTR 36
#define FLASH_SMEM ((128 * FSTR + 64 * FSTR + 64 * FSTR + 128 * FSTR) * 4)

__global__ void __launch_bounds__(128) flash_h_kernel() {
    extern __shared__ uint32_t sm[];
    uint32_t* Qs = sm;
    uint32_t* Ks = Qs + 128 * FSTR;
    uint32_t* Vt = Ks + 64 * FSTR;
    uint32_t* Ps = Vt + 64 * FSTR;

    const int tid = threadIdx.x;
    const int wid = tid >> 5;
    const int lane = tid & 31;
    const int gID = lane >> 2;
    const int tig = lane & 3;
    const int qt = blockIdx.x;
    const int bh = blockIdx.y;
    const int b = bh >> 4;
    const int h = bh & 15;
    const int wq0 = wid * 32;

    const size_t base_q = (size_t)(b * NN + qt * 128) * C3 + (size_t)h * DD;
#pragma unroll
    for (int i = 0; i < 16; i++) {
        int idx = tid + i * 128;
        int row = idx >> 4, c4 = (idx & 15) * 4;
        float4 v = *reinterpret_cast<const float4*>(&g_qkv[base_q + (size_t)row * C3 + c4]);
        uint2 u = make_uint2(f2h2(v.x * 0.125f, v.y * 0.125f),
                             f2h2(v.z * 0.125f, v.w * 0.125f));
        *reinterpret_cast<uint2*>(&Qs[row * FSTR + (idx & 15) * 2]) = u;
    }

    float m[2][2], l[2][2], o[2][8][4];
#pragma unroll
    for (int mi = 0; mi < 2; mi++) {
        m[mi][0] = -1e30f; m[mi][1] = -1e30f;
        l[mi][0] = 0.f; l[mi][1] = 0.f;
#pragma unroll
        for (int nf = 0; nf < 8; nf++)
#pragma unroll
            for (int j = 0; j < 4; j++) o[mi][nf][j] = 0.f;
    }

    const int kv2 = tid & 31;
    const int dg = tid >> 5;

    for (int kt = 0; kt < NN / 64; kt++) {
        __syncthreads();
        const size_t base_k = (size_t)(b * NN + kt * 64) * C3 + CC + (size_t)h * DD;
        const size_t base_v = base_k + CC;

#pragma unroll
        for (int i = 0; i < 8; i++) {
            int idx = tid + i * 128;
            int row = idx >> 4, c4 = (idx & 15) * 4;
            float4 kv = *reinterpret_cast<const float4*>(&g_qkv[base_k + (size_t)row * C3 + c4]);
            uint2 u = make_uint2(f2h2(kv.x, kv.y), f2h2(kv.z, kv.w));
            *reinterpret_cast<uint2*>(&Ks[row * FSTR + (idx & 15) * 2]) = u;
        }

        {
            const float* r0p = &g_qkv[base_v + (size_t)(2 * kv2) * C3 + dg * 16];
            const float* r1p = r0p + C3;
            float4 a0 = *reinterpret_cast<const float4*>(r0p + 0);
            float4 a1 = *reinterpret_cast<const float4*>(r0p + 4);
            float4 a2 = *reinterpret_cast<const float4*>(r0p + 8);
            float4 a3 = *reinterpret_cast<const float4*>(r0p + 12);
            float4 c0 = *reinterpret_cast<const float4*>(r1p + 0);
            float4 c1 = *reinterpret_cast<const float4*>(r1p + 4);
            float4 c2 = *reinterpret_cast<const float4*>(r1p + 8);
            float4 c3 = *reinterpret_cast<const float4*>(r1p + 12);
            uint32_t* vt = &Vt[(dg * 16) * FSTR + kv2];
            vt[0 * FSTR]  = f2h2(a0.x, c0.x);
            vt[1 * FSTR]  = f2h2(a0.y, c0.y);
            vt[2 * FSTR]  = f2h2(a0.z, c0.z);
            vt[3 * FSTR]  = f2h2(a0.w, c0.w);
            vt[4 * FSTR]  = f2h2(a1.x, c1.x);
            vt[5 * FSTR]  = f2h2(a1.y, c1.y);
            vt[6 * FSTR]  = f2h2(a1.z, c1.z);
            vt[7 * FSTR]  = f2h2(a1.w, c1.w);
            vt[8 * FSTR]  = f2h2(a2.x, c2.x);
            vt[9 * FSTR]  = f2h2(a2.y, c2.y);
            vt[10 * FSTR] = f2h2(a2.z, c2.z);
            vt[11 * FSTR] = f2h2(a2.w, c2.w);
            vt[12 * FSTR] = f2h2(a3.x, c3.x);
            vt[13 * FSTR] = f2h2(a3.y, c3.y);
            vt[14 * FSTR] = f2h2(a3.z, c3.z);
            vt[15 * FSTR] = f2h2(a3.w, c3.w);
        }
        __syncthreads();

        float s[2][8][4];
#pragma unroll
        for (int mi = 0; mi < 2; mi++)
#pragma unroll
            for (int nf = 0; nf < 8; nf++)
#pragma unroll
                for (int j = 0; j < 4; j++) s[mi][nf][j] = 0.f;

#pragma unroll
        for (int j = 0; j < 4; j++) {
            const int k0 = j * 8;
            uint32_t a[2][4];
#pragma unroll
            for (int mi = 0; mi < 2; mi++) {
                int rr = wq0 + mi * 16;
                a[mi][0] = Qs[(rr + gID) * FSTR + k0 + tig];
                a[mi][1] = Qs[(rr + gID + 8) * FSTR + k0 + tig];
                a[mi][2] = Qs[(rr + gID) * FSTR + k0 + tig + 4];
                a[mi][3] = Qs[(rr + gID + 8) * FSTR + k0 + tig + 4];
            }
#pragma unroll
            for (int nf = 0; nf < 8; nf++) {
                uint32_t b0 = Ks[(nf * 8 + gID) * FSTR + k0 + tig];
                uint32_t b1 = Ks[(nf * 8 + gID) * FSTR + k0 + tig + 4];
                MMA_F16(s[0][nf], a[0][0], a[0][1], a[0][2], a[0][3], b0, b1);
                MMA_F16(s[1][nf], a[1][0], a[1][1], a[1][2], a[1][3], b0, b1);
            }
        }

#pragma unroll
        for (int mi = 0; mi < 2; mi++) {
            float mx0 = -1e30f, mx1 = -1e30f;
#pragma unroll
            for (int nf = 0; nf < 8; nf++) {
                mx0 = fmaxf(mx0, fmaxf(s[mi][nf][0], s[mi][nf][1]));
                mx1 = fmaxf(mx1, fmaxf(s[mi][nf][2], s[mi][nf][3]));
            }
            mx0 = fmaxf(mx0, __shfl_xor_sync(0xffffffffu, mx0, 1));
            mx0 = fmaxf(mx0, __shfl_xor_sync(0xffffffffu, mx0, 2));
            mx1 = fmaxf(mx1, __shfl_xor_sync(0xffffffffu, mx1, 1));
            mx1 = fmaxf(mx1, __shfl_xor_sync(0xffffffffu, mx1, 2));

            float mn0 = fmaxf(m[mi][0], mx0), mn1 = fmaxf(m[mi][1], mx1);
            float corr0 = __expf(m[mi][0] - mn0), corr1 = __expf(m[mi][1] - mn1);
            float rs0 = 0.f, rs1 = 0.f;
            int rr = wq0 + mi * 16;
#pragma unroll
            for (int nf = 0; nf < 8; nf++) {
                s[mi][nf][0] = __expf(s[mi][nf][0] - mn0);
                s[mi][nf][1] = __expf(s[mi][nf][1] - mn0);
                s[mi][nf][2] = __expf(s[mi][nf][2] - mn1);
                s[mi][nf][3] = __expf(s[mi][nf][3] - mn1);
                rs0 += s[mi][nf][0] + s[mi][nf][1];
                rs1 += s[mi][nf][2] + s[mi][nf][3];
                Ps[(rr + gID) * FSTR + nf * 4 + tig]     = f2h2(s[mi][nf][0], s[mi][nf][1]);
                Ps[(rr + gID + 8) * FSTR + nf * 4 + tig] = f2h2(s[mi][nf][2], s[mi][nf][3]);
            }
            rs0 += __shfl_xor_sync(0xffffffffu, rs0, 1);
            rs0 += __shfl_xor_sync(0xffffffffu, rs0, 2);
            rs1 += __shfl_xor_sync(0xffffffffu, rs1, 1);
            rs1 += __shfl_xor_sync(0xffffffffu, rs1, 2);
            l[mi][0] = l[mi][0] * corr0 + rs0;
            l[mi][1] = l[mi][1] * corr1 + rs1;
            m[mi][0] = mn0; m[mi][1] = mn1;
#pragma unroll
            for (int nf = 0; nf < 8; nf++) {
                o[mi][nf][0] *= corr0; o[mi][nf][1] *= corr0;
                o[mi][nf][2] *= corr1; o[mi][nf][3] *= corr1;
            }
        }
        __syncwarp();

#pragma unroll
        for (int j = 0; j < 4; j++) {
            const int k0 = j * 8;
            uint32_t a[2][4];
#pragma unroll
            for (int mi = 0; mi < 2; mi++) {
                int rr = wq0 + mi * 16;
                a[mi][0] = Ps[(rr + gID) * FSTR + k0 + tig];
                a[mi][1] = Ps[(rr + gID + 8) * FSTR + k0 + tig];
                a[mi][2] = Ps[(rr + gID) * FSTR + k0 + tig + 4];
                a[mi][3] = Ps[(rr + gID + 8) * FSTR + k0 + tig + 4];
            }
#pragma unroll
            for (int nf = 0; nf < 8; nf++) {
                uint32_t b0 = Vt[(nf * 8 + gID) * FSTR + k0 + tig];
                uint32_t b1 = Vt[(nf * 8 + gID) * FSTR + k0 + tig + 4];
                MMA_F16(o[0][nf], a[0][0], a[0][1], a[0][2], a[0][3], b0, b1);
                MMA_F16(o[1][nf], a[1][0], a[1][1], a[1][2], a[1][3], b0, b1);
            }
        }
    }

#pragma unroll
    for (int mi = 0; mi < 2; mi++) {
        float inv0 = 1.0f / l[mi][0], inv1 = 1.0f / l[mi][1];
        int row0 = qt * 128 + wq0 + mi * 16 + gID;
#pragma unroll
        for (int nf = 0; nf < 8; nf++) {
            int col = h * DD + nf * 8 + 2 * tig;
            *reinterpret_cast<uint32_t*>(g_oh + (size_t)(b * NN + row0) * CC + col) =
                f2h2(o[mi][nf][0] * inv0, o[mi][nf][1] * inv0);
            *reinterpret_cast<uint32_t*>(g_oh + (size_t)(b * NN + row0 + 8) * CC + col) =
                f2h2(o[mi][nf][2] * inv1, o[mi][nf][3] * inv1);
        }
    }
}

// ----------------------------------------------------------------------------
extern "C" void kernel_launch(void* const* d_in, const int* in_sizes, int n_in,
                              void* d_out, int out_size) {
    const float* x      = (const float*)d_in[0];
    const float* w_qkv  = (const float*)d_in[1];
    const float* b_qkv  = (const float*)d_in[2];
    const float* gq     = (const float*)d_in[3];
    const float* gk     = (const float*)d_in[4];
    const float* w_proj = (const float*)d_in[5];
    const float* b_proj = (const float*)d_in[6];
    float* out = (float*)d_out;

    float* qkv_ptr = nullptr;
    __half *xh = nullptr, *oh = nullptr, *wqkvTh = nullptr, *wprojTh = nullptr;
    cudaGetSymbolAddress((void**)&qkv_ptr, g_qkv);
    cudaGetSymbolAddress((void**)&xh, g_xh);
    cudaGetSymbolAddress((void**)&oh, g_oh);
    cudaGetSymbolAddress((void**)&wqkvTh, g_wqkvTh);
    cudaGetSymbolAddress((void**)&wprojTh, g_wprojTh);

    // 0) weight transpose+convert, x convert
    {
        dim3 blk(32, 8);
        transpose_h_kernel<<<dim3(C3 / 32, CC / 32), blk>>>(w_qkv, wqkvTh, CC, C3);
        transpose_h_kernel<<<dim3(CC / 32, CC / 32), blk>>>(w_proj, wprojTh, CC, CC);
        hconv_kernel<<<(MM * CC / 8) / 256, 256>>>(x, xh);
    }

    // 1) QKV GEMM
    {
        dim3 grid(C3 / 128, MM / 128);
        gemm_h_kernel<<<grid, 256>>>(xh, wqkvTh, b_qkv, qkv_ptr, MM, C3, CC);
    }

    // 2) head layernorm q,k in place (f32)
    {
        int total_warps = 2 * MM * HH;
        qk_norm_kernel<<<total_warps / 8, 256>>>(gq, gk);
    }

    // 3) flash attention (fp16 mma)
    {
        cudaFuncSetAttribute(flash_h_kernel, cudaFuncAttributeMaxDynamicSharedMemorySize, FLASH_SMEM);
        dim3 grid(NN / 128, BB * HH);
        flash_h_kernel<<<grid, 128, FLASH_SMEM>>>();
    }

    // 4) output projection
    {
        dim3 grid(CC / 128, MM / 128);
        gemm_h_kernel<<<grid, 256>>>(oh, wprojTh, b_proj, out, MM, CC, CC);
    }
}

// round 11
// speedup vs baseline: 6.9895x; 1.2464x over previous
#include <cuda_runtime.h>
#include <cuda_fp16.h>
#include <cstdint>
#include <math.h>

// Problem constants
#define BB 4
#define NN 2048
#define CC 1024
#define HH 16
#define DD 64
#define MM (BB * NN)          // 8192
#define C3 (3 * CC)           // 3072
#define EPSV 1e-6f

// Scratch (16B-aligned)
__device__ __align__(16) float  g_qkv[(size_t)MM * C3];       // 96 MB (GEMM out, LN in)
__device__ __align__(16) __half g_xh[(size_t)MM * CC];        // 16 MB
__device__ __align__(16) __half g_oh[(size_t)MM * CC];        // 16 MB
__device__ __align__(16) __half g_wqkvTh[(size_t)C3 * CC];    // 6 MB
__device__ __align__(16) __half g_wprojTh[(size_t)CC * CC];   // 2 MB
__device__ __align__(16) __half g_qh[(size_t)BB * HH * NN * DD]; // 16 MB (LN(q)*0.125)
__device__ __align__(16) __half g_kh[(size_t)BB * HH * NN * DD]; // 16 MB
__device__ __align__(16) __half g_vh[(size_t)BB * HH * NN * DD]; // 16 MB

__device__ __forceinline__ uint32_t f2h2(float lo, float hi) {
    __half2 h = __float22half2_rn(make_float2(lo, hi));
    return *reinterpret_cast<uint32_t*>(&h);
}
__device__ __forceinline__ uint32_t smem_u32(const void* p) {
    uint32_t a;
    asm("{ .reg .u64 t; cvta.to.shared.u64 t, %1; cvt.u32.u64 %0, t; }" : "=r"(a) : "l"(p));
    return a;
}

#define MMA_F16(c, a0, a1, a2, a3, b0, b1)                                     \
    asm volatile(                                                               \
        "mma.sync.aligned.m16n8k16.row.col.f32.f16.f16.f32 "                    \
        "{%0,%1,%2,%3}, {%4,%5,%6,%7}, {%8,%9}, {%0,%1,%2,%3};"                 \
        : "+f"((c)[0]), "+f"((c)[1]), "+f"((c)[2]), "+f"((c)[3])                \
        : "r"(a0), "r"(a1), "r"(a2), "r"(a3), "r"(b0), "r"(b1))

#define LDM_X4(r0, r1, r2, r3, addr)                                           \
    asm volatile("ldmatrix.sync.aligned.m8n8.x4.shared.b16 {%0,%1,%2,%3}, [%4];" \
        : "=r"(r0), "=r"(r1), "=r"(r2), "=r"(r3) : "r"(addr))

#define LDM_X4_T(r0, r1, r2, r3, addr)                                         \
    asm volatile("ldmatrix.sync.aligned.m8n8.x4.trans.shared.b16 {%0,%1,%2,%3}, [%4];" \
        : "=r"(r0), "=r"(r1), "=r"(r2), "=r"(r3) : "r"(addr))

// ---------------------------------------------------------------------------
// Weight transpose + fp16 convert
// ---------------------------------------------------------------------------
__global__ void transpose_h_kernel(const float* __restrict__ in, __half* __restrict__ out,
                                   int R, int Cn) {
    __shared__ float t[32][33];
    int bx = blockIdx.x * 32, by = blockIdx.y * 32;
#pragma unroll
    for (int i = 0; i < 32; i += 8)
        t[threadIdx.y + i][threadIdx.x] = in[(size_t)(by + threadIdx.y + i) * Cn + bx + threadIdx.x];
    __syncthreads();
#pragma unroll
    for (int i = 0; i < 32; i += 8)
        out[(size_t)(bx + threadIdx.y + i) * R + by + threadIdx.x] =
            __float2half(t[threadIdx.x][threadIdx.y + i]);
}

// ---------------------------------------------------------------------------
// f32 -> fp16 bulk convert (8 elems/thread)
// ---------------------------------------------------------------------------
__global__ void hconv_kernel(const float* __restrict__ src, __half* __restrict__ dst) {
    size_t i = (size_t)blockIdx.x * blockDim.x + threadIdx.x;
    const float4* p = reinterpret_cast<const float4*>(src) + 2 * i;
    float4 a = p[0], b = p[1];
    uint4 u;
    u.x = f2h2(a.x, a.y); u.y = f2h2(a.z, a.w);
    u.z = f2h2(b.x, b.y); u.w = f2h2(b.z, b.w);
    reinterpret_cast<uint4*>(dst)[i] = u;
}

// ---------------------------------------------------------------------------
// fp16 mma.sync GEMM with ldmatrix (R10 exact)
// ---------------------------------------------------------------------------
#define GSTR 20
#define GEMM_BUF_BYTES (128 * GSTR * 4)

__global__ void __launch_bounds__(256)
gemm_h_kernel(const __half* __restrict__ Ah, const __half* __restrict__ BTh,
              const float* __restrict__ bias, float* __restrict__ Cmat,
              int M, int N, int K) {
    __shared__ uint32_t As2[2][128 * GSTR];
    __shared__ uint32_t Bs2[2][128 * GSTR];

    const int tid = threadIdx.x;
    const int wid = tid >> 5;
    const int lane = tid & 31;
    const int gID = lane >> 2;
    const int tig = lane & 3;
    const int grp = lane >> 3;
    const int l8 = lane & 7;
    const int wm = (wid & 1) * 64;
    const int wn = (wid >> 1) * 32;
    const int bm = blockIdx.y * 128;
    const int bn = blockIdx.x * 128;

    const int lrow = tid >> 1;
    const int lhalf = (tid & 1) * 8;
    const __half* Agp = Ah + (size_t)(bm + lrow) * K + (tid & 1) * 16;
    const __half* Bgp = BTh + (size_t)(bn + lrow) * K + (tid & 1) * 16;

    const uint32_t asBase = smem_u32(As2);
    const uint32_t bsBase = smem_u32(Bs2);
    uint32_t aAddr[4], bAddr[2];
#pragma unroll
    for (int mi = 0; mi < 4; mi++)
        aAddr[mi] = asBase + (((wm + mi * 16 + (grp & 1) * 8 + l8) * GSTR) + (grp >> 1) * 4) * 4;
#pragma unroll
    for (int ni2 = 0; ni2 < 2; ni2++)
        bAddr[ni2] = bsBase + (((wn + ni2 * 16 + (grp >> 1) * 8 + l8) * GSTR) + (grp & 1) * 4) * 4;

    float acc[4][4][4];
#pragma unroll
    for (int mi = 0; mi < 4; mi++)
#pragma unroll
        for (int ni = 0; ni < 4; ni++)
#pragma unroll
            for (int r = 0; r < 4; r++) acc[mi][ni][r] = 0.f;

    uint4 rA0 = *reinterpret_cast<const uint4*>(Agp);
    uint4 rA1 = *reinterpret_cast<const uint4*>(Agp + 8);
    uint4 rB0 = *reinterpret_cast<const uint4*>(Bgp);
    uint4 rB1 = *reinterpret_cast<const uint4*>(Bgp + 8);
    *reinterpret_cast<uint4*>(&As2[0][lrow * GSTR + lhalf]) = rA0;
    *reinterpret_cast<uint4*>(&As2[0][lrow * GSTR + lhalf + 4]) = rA1;
    *reinterpret_cast<uint4*>(&Bs2[0][lrow * GSTR + lhalf]) = rB0;
    *reinterpret_cast<uint4*>(&Bs2[0][lrow * GSTR + lhalf + 4]) = rB1;
    __syncthreads();

    const int S = K / 32;
    for (int s = 0; s < S; s++) {
        const int buf = s & 1;
        const uint32_t bufOff = (uint32_t)buf * GEMM_BUF_BYTES;
        if (s + 1 < S) {
            Agp += 32; Bgp += 32;
            rA0 = *reinterpret_cast<const uint4*>(Agp);
            rA1 = *reinterpret_cast<const uint4*>(Agp + 8);
            rB0 = *reinterpret_cast<const uint4*>(Bgp);
            rB1 = *reinterpret_cast<const uint4*>(Bgp + 8);
        }

#pragma unroll
        for (int j = 0; j < 2; j++) {
            const uint32_t jOff = bufOff + j * 32;
            uint32_t af[4][4], bf[4][2];
#pragma unroll
            for (int mi = 0; mi < 4; mi++)
                LDM_X4(af[mi][0], af[mi][1], af[mi][2], af[mi][3], aAddr[mi] + jOff);
            LDM_X4(bf[0][0], bf[0][1], bf[1][0], bf[1][1], bAddr[0] + jOff);
            LDM_X4(bf[2][0], bf[2][1], bf[3][0], bf[3][1], bAddr[1] + jOff);
#pragma unroll
            for (int mi = 0; mi < 4; mi++)
#pragma unroll
                for (int ni = 0; ni < 4; ni++)
                    MMA_F16(acc[mi][ni], af[mi][0], af[mi][1], af[mi][2], af[mi][3],
                            bf[ni][0], bf[ni][1]);
        }

        if (s + 1 < S) {
            *reinterpret_cast<uint4*>(&As2[buf ^ 1][lrow * GSTR + lhalf]) = rA0;
            *reinterpret_cast<uint4*>(&As2[buf ^ 1][lrow * GSTR + lhalf + 4]) = rA1;
            *reinterpret_cast<uint4*>(&Bs2[buf ^ 1][lrow * GSTR + lhalf]) = rB0;
            *reinterpret_cast<uint4*>(&Bs2[buf ^ 1][lrow * GSTR + lhalf + 4]) = rB1;
            __syncthreads();
        }
    }

#pragma unroll
    for (int mi = 0; mi < 4; mi++) {
        int row0 = bm + wm + mi * 16 + gID;
#pragma unroll
        for (int ni = 0; ni < 4; ni++) {
            int col = bn + wn + ni * 8 + 2 * tig;
            float b0 = bias[col], b1 = bias[col + 1];
            float2 v0 = make_float2(acc[mi][ni][0] + b0, acc[mi][ni][1] + b1);
            float2 v1 = make_float2(acc[mi][ni][2] + b0, acc[mi][ni][3] + b1);
            *reinterpret_cast<float2*>(Cmat + (size_t)row0 * N + col) = v0;
            *reinterpret_cast<float2*>(Cmat + (size_t)(row0 + 8) * N + col) = v1;
        }
    }
}

// ----------------------------------------------------------------------------
// Head LayerNorm on q,k + v passthrough -> fp16 [bh][n][d].
// q additionally scaled by 0.125. One warp per (row, comp), comp 0..2.
// ----------------------------------------------------------------------------
__global__ void qknormv_kernel(const float* __restrict__ gamma_q,
                               const float* __restrict__ gamma_k) {
    int gw = (blockIdx.x * blockDim.x + threadIdx.x) >> 5;
    int lane = threadIdx.x & 31;
    int comp = gw % 3;
    int r = gw / 3;                 // [0, MM*HH)
    int h = r & (HH - 1);
    int bn = r >> 4;                // b*NN + n
    int b = bn >> 11, n = bn & (NN - 1);

    const float* ptr = g_qkv + (size_t)bn * C3 + comp * CC + h * DD;
    float2 v = *reinterpret_cast<const float2*>(ptr + lane * 2);

    size_t dst = ((size_t)(b * HH + h) * NN + n) * DD + lane * 2;

    if (comp == 2) {
        *reinterpret_cast<uint32_t*>(g_vh + dst) = f2h2(v.x, v.y);
        return;
    }

    float s = v.x + v.y;
#pragma unroll
    for (int off = 16; off >= 1; off >>= 1) s += __shfl_xor_sync(0xffffffffu, s, off);
    float mu = s * (1.0f / 64.0f);

    float dx = v.x - mu, dy = v.y - mu;
    float e = dx * dx + dy * dy;
#pragma unroll
    for (int off = 16; off >= 1; off >>= 1) e += __shfl_xor_sync(0xffffffffu, e, off);
    float rs = rsqrtf(e * (1.0f / 64.0f) + EPSV);

    const float* gamma = comp ? gamma_k : gamma_q;
    float sc = comp ? 1.0f : 0.125f;
    float ox = dx * rs * gamma[lane * 2 + 0] * sc;
    float oy = dy * rs * gamma[lane * 2 + 1] * sc;
    __half* out = comp ? g_kh : g_qh;
    *reinterpret_cast<uint32_t*>(out + dst) = f2h2(ox, oy);
}

// ----------------------------------------------------------------------------
// Flash attention v3: fp16-native inputs, ldmatrix.trans for V.
// CTA = 128 q rows, 4 warps, KV tile 64. Strides 36 u32.
// ----------------------------------------------------------------------------
#define FSTR 36
#define FLASH_SMEM ((128 * FSTR + 64 * FSTR + 64 * FSTR + 128 * FSTR) * 4)

__global__ void __launch_bounds__(128) flash_h_kernel() {
    extern __shared__ uint32_t sm[];
    uint32_t* Qs = sm;                    // 128 rows x 32 u32 (d-pairs)
    uint32_t* Ks = Qs + 128 * FSTR;       // 64 rows x 32 u32 (d-pairs)
    uint32_t* Vs = Ks + 64 * FSTR;        // 64 kv-rows x 32 u32 (d-pairs, row-major)
    uint32_t* Ps = Vs + 64 * FSTR;        // 128 rows x 32 u32 (kv-pairs)

    const int tid = threadIdx.x;
    const int wid = tid >> 5;
    const int lane = tid & 31;
    const int gID = lane >> 2;
    const int tig = lane & 3;
    const int grp = lane >> 3;
    const int l8 = lane & 7;
    const int qt = blockIdx.x;
    const int bh = blockIdx.y;
    const int b = bh >> 4;
    const int h = bh & 15;
    const int wq0 = wid * 32;

    // V trans-ldmatrix base address (j=0, nf0=0):
    //   mat0: kv row (grp&1)*8 + l8,  u32 col (grp>>1)*4
    const uint32_t vsBase = smem_u32(sm) + (64 * FSTR + 64 * FSTR + 128 * FSTR) * 0; // placeholder
    const uint32_t vAddr0 = smem_u32(Vs) +
        ((((grp & 1) * 8 + l8) * FSTR) + (grp >> 1) * 4) * 4;

    // Q tile: 128 rows x 32 u32 fp16, coalesced
    const uint32_t* qg = reinterpret_cast<const uint32_t*>(g_qh) +
                         ((size_t)bh * NN + qt * 128) * 32;
#pragma unroll
    for (int i = 0; i < 8; i++) {
        int idx = tid + i * 128;
        int row = idx >> 3, c4 = (idx & 7) * 4;
        uint4 u = *reinterpret_cast<const uint4*>(qg + row * 32 + c4);
        *reinterpret_cast<uint4*>(&Qs[row * FSTR + c4]) = u;
    }

    float m[2][2], l[2][2], o[2][8][4];
#pragma unroll
    for (int mi = 0; mi < 2; mi++) {
        m[mi][0] = -1e30f; m[mi][1] = -1e30f;
        l[mi][0] = 0.f; l[mi][1] = 0.f;
#pragma unroll
        for (int nf = 0; nf < 8; nf++)
#pragma unroll
            for (int j = 0; j < 4; j++) o[mi][nf][j] = 0.f;
    }

    for (int kt = 0; kt < NN / 64; kt++) {
        __syncthreads();   // prior-iter K/V reads complete (covers Q stores on kt=0)

        // K,V tiles: 64 rows x 32 u32 each, coalesced fp16
        const uint32_t* kg = reinterpret_cast<const uint32_t*>(g_kh) +
                             ((size_t)bh * NN + kt * 64) * 32;
        const uint32_t* vg = reinterpret_cast<const uint32_t*>(g_vh) +
                             ((size_t)bh * NN + kt * 64) * 32;
#pragma unroll
        for (int i = 0; i < 4; i++) {
            int idx = tid + i * 128;
            int row = idx >> 3, c4 = (idx & 7) * 4;
            uint4 uk = *reinterpret_cast<const uint4*>(kg + row * 32 + c4);
            *reinterpret_cast<uint4*>(&Ks[row * FSTR + c4]) = uk;
            uint4 uv = *reinterpret_cast<const uint4*>(vg + row * 32 + c4);
            *reinterpret_cast<uint4*>(&Vs[row * FSTR + c4]) = uv;
        }
        __syncthreads();

        // S = Q @ K^T  (2 m-frags x 8 n-frags, 4 k16 steps)
        float s[2][8][4];
#pragma unroll
        for (int mi = 0; mi < 2; mi++)
#pragma unroll
            for (int nf = 0; nf < 8; nf++)
#pragma unroll
                for (int j = 0; j < 4; j++) s[mi][nf][j] = 0.f;

#pragma unroll
        for (int j = 0; j < 4; j++) {
            const int k0 = j * 8;
            uint32_t a[2][4];
#pragma unroll
            for (int mi = 0; mi < 2; mi++) {
                int rr = wq0 + mi * 16;
                a[mi][0] = Qs[(rr + gID) * FSTR + k0 + tig];
                a[mi][1] = Qs[(rr + gID + 8) * FSTR + k0 + tig];
                a[mi][2] = Qs[(rr + gID) * FSTR + k0 + tig + 4];
                a[mi][3] = Qs[(rr + gID + 8) * FSTR + k0 + tig + 4];
            }
#pragma unroll
            for (int nf = 0; nf < 8; nf++) {
                uint32_t b0 = Ks[(nf * 8 + gID) * FSTR + k0 + tig];
                uint32_t b1 = Ks[(nf * 8 + gID) * FSTR + k0 + tig + 4];
                MMA_F16(s[0][nf], a[0][0], a[0][1], a[0][2], a[0][3], b0, b1);
                MMA_F16(s[1][nf], a[1][0], a[1][1], a[1][2], a[1][3], b0, b1);
            }
        }

        // online softmax per m-frag
#pragma unroll
        for (int mi = 0; mi < 2; mi++) {
            float mx0 = -1e30f, mx1 = -1e30f;
#pragma unroll
            for (int nf = 0; nf < 8; nf++) {
                mx0 = fmaxf(mx0, fmaxf(s[mi][nf][0], s[mi][nf][1]));
                mx1 = fmaxf(mx1, fmaxf(s[mi][nf][2], s[mi][nf][3]));
            }
            mx0 = fmaxf(mx0, __shfl_xor_sync(0xffffffffu, mx0, 1));
            mx0 = fmaxf(mx0, __shfl_xor_sync(0xffffffffu, mx0, 2));
            mx1 = fmaxf(mx1, __shfl_xor_sync(0xffffffffu, mx1, 1));
            mx1 = fmaxf(mx1, __shfl_xor_sync(0xffffffffu, mx1, 2));

            float mn0 = fmaxf(m[mi][0], mx0), mn1 = fmaxf(m[mi][1], mx1);
            float corr0 = __expf(m[mi][0] - mn0), corr1 = __expf(m[mi][1] - mn1);
            float rs0 = 0.f, rs1 = 0.f;
            int rr = wq0 + mi * 16;
#pragma unroll
            for (int nf = 0; nf < 8; nf++) {
                s[mi][nf][0] = __expf(s[mi][nf][0] - mn0);
                s[mi][nf][1] = __expf(s[mi][nf][1] - mn0);
                s[mi][nf][2] = __expf(s[mi][nf][2] - mn1);
                s[mi][nf][3] = __expf(s[mi][nf][3] - mn1);
                rs0 += s[mi][nf][0] + s[mi][nf][1];
                rs1 += s[mi][nf][2] + s[mi][nf][3];
                Ps[(rr + gID) * FSTR + nf * 4 + tig]     = f2h2(s[mi][nf][0], s[mi][nf][1]);
                Ps[(rr + gID + 8) * FSTR + nf * 4 + tig] = f2h2(s[mi][nf][2], s[mi][nf][3]);
            }
            rs0 += __shfl_xor_sync(0xffffffffu, rs0, 1);
            rs0 += __shfl_xor_sync(0xffffffffu, rs0, 2);
            rs1 += __shfl_xor_sync(0xffffffffu, rs1, 1);
            rs1 += __shfl_xor_sync(0xffffffffu, rs1, 2);
            l[mi][0] = l[mi][0] * corr0 + rs0;
            l[mi][1] = l[mi][1] * corr1 + rs1;
            m[mi][0] = mn0; m[mi][1] = mn1;
#pragma unroll
            for (int nf = 0; nf < 8; nf++) {
                o[mi][nf][0] *= corr0; o[mi][nf][1] *= corr0;
                o[mi][nf][2] *= corr1; o[mi][nf][3] *= corr1;
            }
        }
        __syncwarp();

        // O += P @ V   (B-frags via ldmatrix.trans from row-major Vs[kv][d])
#pragma unroll
        for (int j = 0; j < 4; j++) {
            const int k0 = j * 8;
            const uint32_t vj = vAddr0 + j * 16 * FSTR * 4;   // + 16 kv rows
            uint32_t a[2][4], bt[8][2];
#pragma unroll
            for (int mi = 0; mi < 2; mi++) {
                int rr = wq0 + mi * 16;
                a[mi][0] = Ps[(rr + gID) * FSTR + k0 + tig];
                a[mi][1] = Ps[(rr + gID + 8) * FSTR + k0 + tig];
                a[mi][2] = Ps[(rr + gID) * FSTR + k0 + tig + 4];
                a[mi][3] = Ps[(rr + gID + 8) * FSTR + k0 + tig + 4];
            }
#pragma unroll
            for (int nf0 = 0; nf0 < 8; nf0 += 2)
                LDM_X4_T(bt[nf0][0], bt[nf0][1], bt[nf0 + 1][0], bt[nf0 + 1][1],
                         vj + nf0 * 16);   // nf0*4 u32 = nf0*16 bytes
#pragma unroll
            for (int nf = 0; nf < 8; nf++) {
                MMA_F16(o[0][nf], a[0][0], a[0][1], a[0][2], a[0][3], bt[nf][0], bt[nf][1]);
                MMA_F16(o[1][nf], a[1][0], a[1][1], a[1][2], a[1][3], bt[nf][0], bt[nf][1]);
            }
        }
    }

    // normalize + store fp16 to g_oh [b*n][h*d]
#pragma unroll
    for (int mi = 0; mi < 2; mi++) {
        float inv0 = 1.0f / l[mi][0], inv1 = 1.0f / l[mi][1];
        int row0 = qt * 128 + wq0 + mi * 16 + gID;
#pragma unroll
        for (int nf = 0; nf < 8; nf++) {
            int col = h * DD + nf * 8 + 2 * tig;
            *reinterpret_cast<uint32_t*>(g_oh + (size_t)(b * NN + row0) * CC + col) =
                f2h2(o[mi][nf][0] * inv0, o[mi][nf][1] * inv0);
            *reinterpret_cast<uint32_t*>(g_oh + (size_t)(b * NN + row0 + 8) * CC + col) =
                f2h2(o[mi][nf][2] * inv1, o[mi][nf][3] * inv1);
        }
    }
    (void)vsBase;
}

// ----------------------------------------------------------------------------
extern "C" void kernel_launch(void* const* d_in, const int* in_sizes, int n_in,
                              void* d_out, int out_size) {
    const float* x      = (const float*)d_in[0];
    const float* w_qkv  = (const float*)d_in[1];
    const float* b_qkv  = (const float*)d_in[2];
    const float* gq     = (const float*)d_in[3];
    const float* gk     = (const float*)d_in[4];
    const float* w_proj = (const float*)d_in[5];
    const float* b_proj = (const float*)d_in[6];
    float* out = (float*)d_out;

    float* qkv_ptr = nullptr;
    __half *xh = nullptr, *oh = nullptr, *wqkvTh = nullptr, *wprojTh = nullptr;
    cudaGetSymbolAddress((void**)&qkv_ptr, g_qkv);
    cudaGetSymbolAddress((void**)&xh, g_xh);
    cudaGetSymbolAddress((void**)&oh, g_oh);
    cudaGetSymbolAddress((void**)&wqkvTh, g_wqkvTh);
    cudaGetSymbolAddress((void**)&wprojTh, g_wprojTh);

    // 0) weight transpose+convert, x convert
    {
        dim3 blk(32, 8);
        transpose_h_kernel<<<dim3(C3 / 32, CC / 32), blk>>>(w_qkv, wqkvTh, CC, C3);
        transpose_h_kernel<<<dim3(CC / 32, CC / 32), blk>>>(w_proj, wprojTh, CC, CC);
        hconv_kernel<<<(MM * CC / 8) / 256, 256>>>(x, xh);
    }

    // 1) QKV GEMM
    {
        dim3 grid(C3 / 128, MM / 128);
        gemm_h_kernel<<<grid, 256>>>(xh, wqkvTh, b_qkv, qkv_ptr, MM, C3, CC);
    }

    // 2) head layernorm q,k + v passthrough -> fp16 [bh][n][d]
    {
        int total_warps = 3 * MM * HH;
        qknormv_kernel<<<total_warps / 8, 256>>>(gq, gk);
    }

    // 3) flash attention v3 (fp16-native)
    {
        cudaFuncSetAttribute(flash_h_kernel, cudaFuncAttributeMaxDynamicSharedMemorySize, FLASH_SMEM);
        dim3 grid(NN / 128, BB * HH);
        flash_h_kernel<<<grid, 128, FLASH_SMEM>>>();
    }

    // 4) output projection
    {
        dim3 grid(CC / 128, MM / 128);
        gemm_h_kernel<<<grid, 256>>>(oh, wprojTh, b_proj, out, MM, CC, CC);
    }
}